// round 1
// baseline (speedup 1.0000x reference)
#include <cuda_runtime.h>

#define NM 12000
#define ND 10000
#define DIM 64
#define FEAT 512
#define EMAX 1000000
#define LAYERS 3

// ---------------- device scratch (static allocation only) ----------------
__device__ float g_memb[NM * DIM];
__device__ float g_demb[ND * DIM];
__device__ float g_w[EMAX];
__device__ float g_rs_m[NM];
__device__ float g_rs_d[ND];
__device__ int   g_off_m[NM + 1];
__device__ int   g_off_d[ND + 1];
__device__ int   g_cur_m[NM];
__device__ int   g_cur_d[ND];
__device__ int   g_col_m[EMAX];
__device__ float g_val_m[EMAX];
__device__ int   g_col_d[EMAX];
__device__ float g_val_d[EMAX];

__device__ __forceinline__ float tanh_fast(float x) {
    // (e^{2x}-1)/(e^{2x}+1); abs error ~1e-7, fine vs 1e-3 tolerance
    float xc = fminf(fmaxf(x, -12.f), 12.f);
    float e2 = __expf(2.f * xc);
    return __fdividef(e2 - 1.f, e2 + 1.f);
}

// ---------------- init ----------------
__global__ void zero_kernel() {
    int i = blockIdx.x * blockDim.x + threadIdx.x;
    if (i < NM) { g_cur_m[i] = 0; g_rs_m[i] = 0.f; }
    if (i < ND) { g_cur_d[i] = 0; g_rs_d[i] = 0.f; }
}

// ---------------- projection GEMM: C[M][64] = A[M][512] * W[64][512]^T ----
// 256 threads, tile 128 rows x 64 cols, K chunks of 32, 8x4 micro-tile
__global__ __launch_bounds__(256) void proj_kernel(const float* __restrict__ A,
                                                   const float* __restrict__ W,
                                                   int Mrows, int which) {
    float* C = which ? g_demb : g_memb;
    __shared__ float As[128 * 33];
    __shared__ float WsT[32 * 64];
    int tid = threadIdx.x;
    int tx = tid & 15, ty = tid >> 4;
    int row0 = blockIdx.x * 128;

    float acc[8][4];
#pragma unroll
    for (int i = 0; i < 8; i++)
#pragma unroll
        for (int j = 0; j < 4; j++) acc[i][j] = 0.f;

    for (int kc = 0; kc < FEAT; kc += 32) {
        // A tile: 128 rows x 32 k
#pragma unroll
        for (int p = 0; p < 4; p++) {
            int idx = p * 256 + tid;       // float4 index, 0..1023
            int r = idx >> 3;              // 0..127
            int kq = idx & 7;              // 0..7
            int grow = row0 + r;
            float4 v = make_float4(0.f, 0.f, 0.f, 0.f);
            if (grow < Mrows)
                v = *(const float4*)(A + (size_t)grow * FEAT + kc + kq * 4);
            float* dst = &As[r * 33 + kq * 4];
            dst[0] = v.x; dst[1] = v.y; dst[2] = v.z; dst[3] = v.w;
        }
        // W tile transposed: WsT[k][c]
#pragma unroll
        for (int p = 0; p < 2; p++) {
            int idx = p * 256 + tid;       // 0..511
            int c = idx >> 3;              // 0..63
            int kq = idx & 7;
            float4 v = *(const float4*)(W + (size_t)c * FEAT + kc + kq * 4);
            WsT[(kq * 4 + 0) * 64 + c] = v.x;
            WsT[(kq * 4 + 1) * 64 + c] = v.y;
            WsT[(kq * 4 + 2) * 64 + c] = v.z;
            WsT[(kq * 4 + 3) * 64 + c] = v.w;
        }
        __syncthreads();
#pragma unroll 8
        for (int k = 0; k < 32; k++) {
            float4 w = *(const float4*)&WsT[k * 64 + tx * 4];
#pragma unroll
            for (int i = 0; i < 8; i++) {
                float a = As[(ty * 8 + i) * 33 + k];
                acc[i][0] += a * w.x; acc[i][1] += a * w.y;
                acc[i][2] += a * w.z; acc[i][3] += a * w.w;
            }
        }
        __syncthreads();
    }
#pragma unroll
    for (int i = 0; i < 8; i++) {
        int grow = row0 + ty * 8 + i;
        if (grow < Mrows) {
            float4 v = make_float4(acc[i][0], acc[i][1], acc[i][2], acc[i][3]);
            *(float4*)(C + (size_t)grow * DIM + tx * 4) = v;
        }
    }
}

// ---------------- per-edge attention MLP + row-sum / histogram ----------------
// h = tanh(W1 @ relu([m_emb[mi]; d_emb[di]]) + b1); w = exp(W2 @ h)
__global__ __launch_bounds__(256) void edge_mlp_kernel(const float* __restrict__ W1,
                                                       const float* __restrict__ b1,
                                                       const float* __restrict__ W2,
                                                       const int* __restrict__ mi,
                                                       const int* __restrict__ di,
                                                       int E) {
    __shared__ float sW1T[128 * 64];   // [k][j]
    __shared__ float sW2[64];
    __shared__ float sb1[64];
    int tid = threadIdx.x;
#pragma unroll
    for (int p = 0; p < 32; p++) {
        int l = p * 256 + tid;         // 0..8191
        int j = l >> 7;
        int k = l & 127;
        sW1T[k * 64 + j] = W1[l];
    }
    if (tid < 64) { sW2[tid] = W2[tid]; sb1[tid] = b1[tid]; }
    __syncthreads();

    int e = blockIdx.x * blockDim.x + tid;
    if (e >= E) return;
    int m = mi[e], d = di[e];

    float acc[64];
#pragma unroll
    for (int j = 0; j < 64; j++) acc[j] = sb1[j];

    const float4* xm = (const float4*)(g_memb + (size_t)m * DIM);
#pragma unroll 1
    for (int kq = 0; kq < 16; kq++) {
        float4 x4 = xm[kq];
        float xs0 = fmaxf(x4.x, 0.f), xs1 = fmaxf(x4.y, 0.f);
        float xs2 = fmaxf(x4.z, 0.f), xs3 = fmaxf(x4.w, 0.f);
        float xs[4] = {xs0, xs1, xs2, xs3};
#pragma unroll
        for (int s = 0; s < 4; s++) {
            const float4* wr = (const float4*)(sW1T + (kq * 4 + s) * 64);
            float x = xs[s];
#pragma unroll
            for (int j4 = 0; j4 < 16; j4++) {
                float4 w = wr[j4];
                acc[j4 * 4 + 0] += x * w.x; acc[j4 * 4 + 1] += x * w.y;
                acc[j4 * 4 + 2] += x * w.z; acc[j4 * 4 + 3] += x * w.w;
            }
        }
    }
    const float4* xd = (const float4*)(g_demb + (size_t)d * DIM);
#pragma unroll 1
    for (int kq = 0; kq < 16; kq++) {
        float4 x4 = xd[kq];
        float xs0 = fmaxf(x4.x, 0.f), xs1 = fmaxf(x4.y, 0.f);
        float xs2 = fmaxf(x4.z, 0.f), xs3 = fmaxf(x4.w, 0.f);
        float xs[4] = {xs0, xs1, xs2, xs3};
#pragma unroll
        for (int s = 0; s < 4; s++) {
            const float4* wr = (const float4*)(sW1T + (64 + kq * 4 + s) * 64);
            float x = xs[s];
#pragma unroll
            for (int j4 = 0; j4 < 16; j4++) {
                float4 w = wr[j4];
                acc[j4 * 4 + 0] += x * w.x; acc[j4 * 4 + 1] += x * w.y;
                acc[j4 * 4 + 2] += x * w.z; acc[j4 * 4 + 3] += x * w.w;
            }
        }
    }

    float score = 0.f;
#pragma unroll
    for (int j = 0; j < 64; j++) score += tanh_fast(acc[j]) * sW2[j];
    float w = __expf(score);
    g_w[e] = w;
    atomicAdd(&g_rs_m[m], w);
    atomicAdd(&g_rs_d[d], w);
    atomicAdd(&g_cur_m[m], 1);
    atomicAdd(&g_cur_d[d], 1);
}

// ---------------- single-block exclusive scan over counts ----------------
__global__ void scan_kernel(int which) {
    int n = which ? ND : NM;
    int* cnt = which ? g_cur_d : g_cur_m;   // in: counts, out: cursors
    int* off = which ? g_off_d : g_off_m;
    __shared__ int part[1024];
    int t = threadIdx.x;
    int chunk = (n + 1023) >> 10;
    int lo = t * chunk;
    int hi = min(n, lo + chunk);
    int s = 0;
    for (int i = lo; i < hi; i++) s += cnt[i];
    part[t] = s;
    __syncthreads();
    for (int dd = 1; dd < 1024; dd <<= 1) {
        int v = (t >= dd) ? part[t - dd] : 0;
        __syncthreads();
        part[t] += v;
        __syncthreads();
    }
    int run = (t == 0) ? 0 : part[t - 1];
    for (int i = lo; i < hi; i++) {
        int c = cnt[i];
        off[i] = run;
        cnt[i] = run;   // reset as scatter cursor
        run += c;
    }
    if (t == 1023) off[n] = part[1023];
}

// ---------------- scatter edges into CSR (both directions) ----------------
__global__ void scatter_kernel(const int* __restrict__ mi,
                               const int* __restrict__ di, int E) {
    int e = blockIdx.x * blockDim.x + threadIdx.x;
    if (e >= E) return;
    float w = g_w[e];
    int m = mi[e], d = di[e];
    int pm = atomicAdd(&g_cur_m[m], 1);
    g_col_m[pm] = d; g_val_m[pm] = w;
    int pd = atomicAdd(&g_cur_d[d], 1);
    g_col_d[pd] = m; g_val_d[pd] = w;
}

// ---------------- rowsum -> rs^{-beta} (beta = 0.5) ----------------
__global__ void invnorm_kernel() {
    int i = blockIdx.x * blockDim.x + threadIdx.x;
    if (i < NM) { float r = g_rs_m[i]; g_rs_m[i] = (r > 0.f) ? rsqrtf(r) : 0.f; }
    if (i < ND) { float r = g_rs_d[i]; g_rs_d[i] = (r > 0.f) ? rsqrtf(r) : 0.f; }
}

// ---------------- CSR SpMM + tanh + layer accumulation ----------------
// one warp per row; lane handles 2 of 64 columns
__global__ __launch_bounds__(256) void spmm_kernel(float* __restrict__ outacc,
                                                   int dir, int store) {
    const int*   off  = dir ? g_off_d : g_off_m;
    const int*   col  = dir ? g_col_d : g_col_m;
    const float* val  = dir ? g_val_d : g_val_m;
    const float* invn = dir ? g_rs_d : g_rs_m;
    const float* xin  = dir ? g_memb : g_demb;
    float*       xout = dir ? g_demb : g_memb;
    int nrows = dir ? ND : NM;

    int gwarp = (blockIdx.x * blockDim.x + threadIdx.x) >> 5;
    int lane = threadIdx.x & 31;
    if (gwarp >= nrows) return;
    int s = off[gwarp], epos = off[gwarp + 1];

    float a0 = 0.f, a1 = 0.f;
    for (int base = s; base < epos; base += 32) {
        int idx = base + lane;
        int c = 0; float v = 0.f;
        if (idx < epos) { c = col[idx]; v = val[idx]; }
        int nn = min(32, epos - base);
        for (int t = 0; t < nn; t++) {
            int   cc = __shfl_sync(0xffffffffu, c, t);
            float vv = __shfl_sync(0xffffffffu, v, t);
            float2 xv = *(const float2*)(xin + (size_t)cc * DIM + lane * 2);
            a0 += vv * xv.x;
            a1 += vv * xv.y;
        }
    }
    float inv = invn[gwarp];
    float y0 = tanh_fast(a0 * inv);
    float y1 = tanh_fast(a1 * inv);
    float* xo = xout + (size_t)gwarp * DIM + lane * 2;
    xo[0] = y0; xo[1] = y1;
    float* oa = outacc + (size_t)gwarp * DIM + lane * 2;
    if (store) { oa[0] = y0; oa[1] = y1; }
    else       { oa[0] += y0; oa[1] += y1; }
}

// ---------------- launch ----------------
extern "C" void kernel_launch(void* const* d_in, const int* in_sizes, int n_in,
                              void* d_out, int out_size) {
    const float* m_sim = (const float*)d_in[0];
    const float* d_sim = (const float*)d_in[1];
    const float* Wm    = (const float*)d_in[2];
    const float* Wd    = (const float*)d_in[3];
    const float* W1    = (const float*)d_in[4];
    const float* b1    = (const float*)d_in[5];
    const float* W2    = (const float*)d_in[6];
    const int*   mi    = (const int*)d_in[7];
    const int*   di    = (const int*)d_in[8];
    int E = in_sizes[7];
    float* out = (float*)d_out;

    zero_kernel<<<(NM + 255) / 256, 256>>>();
    proj_kernel<<<(NM + 127) / 128, 256>>>(m_sim, Wm, NM, 0);
    proj_kernel<<<(ND + 127) / 128, 256>>>(d_sim, Wd, ND, 1);
    edge_mlp_kernel<<<(E + 255) / 256, 256>>>(W1, b1, W2, mi, di, E);
    scan_kernel<<<1, 1024>>>(0);
    scan_kernel<<<1, 1024>>>(1);
    scatter_kernel<<<(E + 255) / 256, 256>>>(mi, di, E);
    invnorm_kernel<<<(NM + 255) / 256, 256>>>();

    float* out_m = out;
    float* out_d = out + (size_t)NM * DIM;
    for (int l = 0; l < LAYERS; l++) {
        spmm_kernel<<<(NM * 32 + 255) / 256, 256>>>(out_m, 0, l == 0);
        spmm_kernel<<<(ND * 32 + 255) / 256, 256>>>(out_d, 1, l == 0);
    }
}

// round 2
// speedup vs baseline: 2.0941x; 2.0941x over previous
#include <cuda_runtime.h>

#define NM 12000
#define ND 10000
#define DIM 64
#define FEAT 512
#define EMAX 1000000
#define LAYERS 3

// ---------------- device scratch (static allocation only) ----------------
__device__ float g_memb[NM * DIM];
__device__ float g_demb[ND * DIM];
__device__ float g_pm[NM * DIM];     // W1m @ relu(m_emb)  per node
__device__ float g_pd[ND * DIM];     // W1d @ relu(d_emb)  per node
__device__ float g_w[EMAX];
__device__ float g_rs_m[NM];
__device__ float g_rs_d[ND];
__device__ int   g_off_m[NM + 1];
__device__ int   g_off_d[ND + 1];
__device__ int   g_cur_m[NM];
__device__ int   g_cur_d[ND];
__device__ int   g_col_m[EMAX];
__device__ float g_val_m[EMAX];
__device__ int   g_col_d[EMAX];
__device__ float g_val_d[EMAX];

__device__ __forceinline__ float tanh_fast(float x) {
    float xc = fminf(fmaxf(x, -12.f), 12.f);
    float e2 = __expf(2.f * xc);
    return __fdividef(e2 - 1.f, e2 + 1.f);
}

// ---------------- init ----------------
__global__ void zero_kernel() {
    int i = blockIdx.x * blockDim.x + threadIdx.x;
    if (i < NM) { g_cur_m[i] = 0; g_rs_m[i] = 0.f; }
    if (i < ND) { g_cur_d[i] = 0; g_rs_d[i] = 0.f; }
}

// ---------------- projection GEMM: C[M][64] = A[M][512] * W[64][512]^T ----
__global__ __launch_bounds__(256) void proj_kernel(const float* __restrict__ A,
                                                   const float* __restrict__ W,
                                                   int Mrows, int which) {
    float* C = which ? g_demb : g_memb;
    __shared__ float As[128 * 33];
    __shared__ float WsT[32 * 64];
    int tid = threadIdx.x;
    int tx = tid & 15, ty = tid >> 4;
    int row0 = blockIdx.x * 128;

    float acc[8][4];
#pragma unroll
    for (int i = 0; i < 8; i++)
#pragma unroll
        for (int j = 0; j < 4; j++) acc[i][j] = 0.f;

    for (int kc = 0; kc < FEAT; kc += 32) {
#pragma unroll
        for (int p = 0; p < 4; p++) {
            int idx = p * 256 + tid;
            int r = idx >> 3;
            int kq = idx & 7;
            int grow = row0 + r;
            float4 v = make_float4(0.f, 0.f, 0.f, 0.f);
            if (grow < Mrows)
                v = *(const float4*)(A + (size_t)grow * FEAT + kc + kq * 4);
            float* dst = &As[r * 33 + kq * 4];
            dst[0] = v.x; dst[1] = v.y; dst[2] = v.z; dst[3] = v.w;
        }
#pragma unroll
        for (int p = 0; p < 2; p++) {
            int idx = p * 256 + tid;
            int c = idx >> 3;
            int kq = idx & 7;
            float4 v = *(const float4*)(W + (size_t)c * FEAT + kc + kq * 4);
            WsT[(kq * 4 + 0) * 64 + c] = v.x;
            WsT[(kq * 4 + 1) * 64 + c] = v.y;
            WsT[(kq * 4 + 2) * 64 + c] = v.z;
            WsT[(kq * 4 + 3) * 64 + c] = v.w;
        }
        __syncthreads();
#pragma unroll 8
        for (int k = 0; k < 32; k++) {
            float4 w = *(const float4*)&WsT[k * 64 + tx * 4];
#pragma unroll
            for (int i = 0; i < 8; i++) {
                float a = As[(ty * 8 + i) * 33 + k];
                acc[i][0] += a * w.x; acc[i][1] += a * w.y;
                acc[i][2] += a * w.z; acc[i][3] += a * w.w;
            }
        }
        __syncthreads();
    }
#pragma unroll
    for (int i = 0; i < 8; i++) {
        int grow = row0 + ty * 8 + i;
        if (grow < Mrows) {
            float4 v = make_float4(acc[i][0], acc[i][1], acc[i][2], acc[i][3]);
            *(float4*)(C + (size_t)grow * DIM + tx * 4) = v;
        }
    }
}

// ---------------- per-node MLP partial: P = relu(X) @ W1partT ----------------
// X: [Mrows,64] emb; W1 row j has stride 128, offset koff (0 for m, 64 for d)
__global__ __launch_bounds__(256) void pre_mlp_kernel(const float* __restrict__ W1,
                                                      int koff, int which) {
    const float* X = which ? g_demb : g_memb;
    float* P = which ? g_pd : g_pm;
    int Mrows = which ? ND : NM;
    __shared__ float As[128 * 33];
    __shared__ float WsT[32 * 64];
    int tid = threadIdx.x;
    int tx = tid & 15, ty = tid >> 4;
    int row0 = blockIdx.x * 128;

    float acc[8][4];
#pragma unroll
    for (int i = 0; i < 8; i++)
#pragma unroll
        for (int j = 0; j < 4; j++) acc[i][j] = 0.f;

    for (int kc = 0; kc < DIM; kc += 32) {
        // A tile with relu: 128 rows x 32 k
#pragma unroll
        for (int p = 0; p < 4; p++) {
            int idx = p * 256 + tid;
            int r = idx >> 3;
            int kq = idx & 7;
            int grow = row0 + r;
            float4 v = make_float4(0.f, 0.f, 0.f, 0.f);
            if (grow < Mrows)
                v = *(const float4*)(X + (size_t)grow * DIM + kc + kq * 4);
            float* dst = &As[r * 33 + kq * 4];
            dst[0] = fmaxf(v.x, 0.f); dst[1] = fmaxf(v.y, 0.f);
            dst[2] = fmaxf(v.z, 0.f); dst[3] = fmaxf(v.w, 0.f);
        }
        // W tile: WsT[k][j] = W1[j*128 + koff + kc + k]
#pragma unroll
        for (int p = 0; p < 2; p++) {
            int idx = p * 256 + tid;
            int c = idx >> 3;
            int kq = idx & 7;
            float4 v = *(const float4*)(W1 + (size_t)c * 128 + koff + kc + kq * 4);
            WsT[(kq * 4 + 0) * 64 + c] = v.x;
            WsT[(kq * 4 + 1) * 64 + c] = v.y;
            WsT[(kq * 4 + 2) * 64 + c] = v.z;
            WsT[(kq * 4 + 3) * 64 + c] = v.w;
        }
        __syncthreads();
#pragma unroll 8
        for (int k = 0; k < 32; k++) {
            float4 w = *(const float4*)&WsT[k * 64 + tx * 4];
#pragma unroll
            for (int i = 0; i < 8; i++) {
                float a = As[(ty * 8 + i) * 33 + k];
                acc[i][0] += a * w.x; acc[i][1] += a * w.y;
                acc[i][2] += a * w.z; acc[i][3] += a * w.w;
            }
        }
        __syncthreads();
    }
#pragma unroll
    for (int i = 0; i < 8; i++) {
        int grow = row0 + ty * 8 + i;
        if (grow < Mrows) {
            float4 v = make_float4(acc[i][0], acc[i][1], acc[i][2], acc[i][3]);
            *(float4*)(P + (size_t)grow * DIM + tx * 4) = v;
        }
    }
}

// ---------------- light per-edge kernel: gather partials, tanh, dot, exp ----
__global__ __launch_bounds__(256) void edge_light_kernel(const float* __restrict__ b1,
                                                         const float* __restrict__ W2,
                                                         const int* __restrict__ mi,
                                                         const int* __restrict__ di,
                                                         int E) {
    __shared__ float4 sb1[16];
    __shared__ float4 sW2[16];
    int tid = threadIdx.x;
    if (tid < 16) {
        sb1[tid] = ((const float4*)b1)[tid];
        sW2[tid] = ((const float4*)W2)[tid];
    }
    __syncthreads();

    int e = blockIdx.x * blockDim.x + tid;
    if (e >= E) return;
    int m = mi[e], d = di[e];

    const float4* pm = (const float4*)(g_pm + (size_t)m * DIM);
    const float4* pd = (const float4*)(g_pd + (size_t)d * DIM);

    float score = 0.f;
#pragma unroll
    for (int q = 0; q < 16; q++) {
        float4 a = pm[q];
        float4 b = pd[q];
        float4 bb = sb1[q];
        float4 w2 = sW2[q];
        score += tanh_fast(a.x + b.x + bb.x) * w2.x;
        score += tanh_fast(a.y + b.y + bb.y) * w2.y;
        score += tanh_fast(a.z + b.z + bb.z) * w2.z;
        score += tanh_fast(a.w + b.w + bb.w) * w2.w;
    }
    float w = __expf(score);
    g_w[e] = w;
    atomicAdd(&g_rs_m[m], w);
    atomicAdd(&g_rs_d[d], w);
    atomicAdd(&g_cur_m[m], 1);
    atomicAdd(&g_cur_d[d], 1);
}

// ---------------- single-block exclusive scan over counts ----------------
__global__ void scan_kernel(int which) {
    int n = which ? ND : NM;
    int* cnt = which ? g_cur_d : g_cur_m;
    int* off = which ? g_off_d : g_off_m;
    __shared__ int part[1024];
    int t = threadIdx.x;
    int chunk = (n + 1023) >> 10;
    int lo = t * chunk;
    int hi = min(n, lo + chunk);
    int s = 0;
    for (int i = lo; i < hi; i++) s += cnt[i];
    part[t] = s;
    __syncthreads();
    for (int dd = 1; dd < 1024; dd <<= 1) {
        int v = (t >= dd) ? part[t - dd] : 0;
        __syncthreads();
        part[t] += v;
        __syncthreads();
    }
    int run = (t == 0) ? 0 : part[t - 1];
    for (int i = lo; i < hi; i++) {
        int c = cnt[i];
        off[i] = run;
        cnt[i] = run;
        run += c;
    }
    if (t == 1023) off[n] = part[1023];
}

// ---------------- scatter edges into CSR (both directions) ----------------
__global__ void scatter_kernel(const int* __restrict__ mi,
                               const int* __restrict__ di, int E) {
    int e = blockIdx.x * blockDim.x + threadIdx.x;
    if (e >= E) return;
    float w = g_w[e];
    int m = mi[e], d = di[e];
    int pm = atomicAdd(&g_cur_m[m], 1);
    g_col_m[pm] = d; g_val_m[pm] = w;
    int pd = atomicAdd(&g_cur_d[d], 1);
    g_col_d[pd] = m; g_val_d[pd] = w;
}

// ---------------- rowsum -> rs^{-beta} (beta = 0.5) ----------------
__global__ void invnorm_kernel() {
    int i = blockIdx.x * blockDim.x + threadIdx.x;
    if (i < NM) { float r = g_rs_m[i]; g_rs_m[i] = (r > 0.f) ? rsqrtf(r) : 0.f; }
    if (i < ND) { float r = g_rs_d[i]; g_rs_d[i] = (r > 0.f) ? rsqrtf(r) : 0.f; }
}

// ---------------- CSR SpMM + tanh + layer accumulation ----------------
__global__ __launch_bounds__(256) void spmm_kernel(float* __restrict__ outacc,
                                                   int dir, int store) {
    const int*   off  = dir ? g_off_d : g_off_m;
    const int*   col  = dir ? g_col_d : g_col_m;
    const float* val  = dir ? g_val_d : g_val_m;
    const float* invn = dir ? g_rs_d : g_rs_m;
    const float* xin  = dir ? g_memb : g_demb;
    float*       xout = dir ? g_demb : g_memb;
    int nrows = dir ? ND : NM;

    int gwarp = (blockIdx.x * blockDim.x + threadIdx.x) >> 5;
    int lane = threadIdx.x & 31;
    if (gwarp >= nrows) return;
    int s = off[gwarp], epos = off[gwarp + 1];

    float a0 = 0.f, a1 = 0.f;
    for (int base = s; base < epos; base += 32) {
        int idx = base + lane;
        int c = 0; float v = 0.f;
        if (idx < epos) { c = col[idx]; v = val[idx]; }
        int nn = min(32, epos - base);
        for (int t = 0; t < nn; t++) {
            int   cc = __shfl_sync(0xffffffffu, c, t);
            float vv = __shfl_sync(0xffffffffu, v, t);
            float2 xv = *(const float2*)(xin + (size_t)cc * DIM + lane * 2);
            a0 += vv * xv.x;
            a1 += vv * xv.y;
        }
    }
    float inv = invn[gwarp];
    float y0 = tanh_fast(a0 * inv);
    float y1 = tanh_fast(a1 * inv);
    float* xo = xout + (size_t)gwarp * DIM + lane * 2;
    xo[0] = y0; xo[1] = y1;
    float* oa = outacc + (size_t)gwarp * DIM + lane * 2;
    if (store) { oa[0] = y0; oa[1] = y1; }
    else       { oa[0] += y0; oa[1] += y1; }
}

// ---------------- launch ----------------
extern "C" void kernel_launch(void* const* d_in, const int* in_sizes, int n_in,
                              void* d_out, int out_size) {
    const float* m_sim = (const float*)d_in[0];
    const float* d_sim = (const float*)d_in[1];
    const float* Wm    = (const float*)d_in[2];
    const float* Wd    = (const float*)d_in[3];
    const float* W1    = (const float*)d_in[4];
    const float* b1    = (const float*)d_in[5];
    const float* W2    = (const float*)d_in[6];
    const int*   mi    = (const int*)d_in[7];
    const int*   di    = (const int*)d_in[8];
    int E = in_sizes[7];
    float* out = (float*)d_out;

    zero_kernel<<<(NM + 255) / 256, 256>>>();
    proj_kernel<<<(NM + 127) / 128, 256>>>(m_sim, Wm, NM, 0);
    proj_kernel<<<(ND + 127) / 128, 256>>>(d_sim, Wd, ND, 1);
    pre_mlp_kernel<<<(NM + 127) / 128, 256>>>(W1, 0, 0);
    pre_mlp_kernel<<<(ND + 127) / 128, 256>>>(W1, 64, 1);
    edge_light_kernel<<<(E + 255) / 256, 256>>>(b1, W2, mi, di, E);
    scan_kernel<<<1, 1024>>>(0);
    scan_kernel<<<1, 1024>>>(1);
    scatter_kernel<<<(E + 255) / 256, 256>>>(mi, di, E);
    invnorm_kernel<<<(NM + 255) / 256, 256>>>();

    float* out_m = out;
    float* out_d = out + (size_t)NM * DIM;
    for (int l = 0; l < LAYERS; l++) {
        spmm_kernel<<<(NM * 32 + 255) / 256, 256>>>(out_m, 0, l == 0);
        spmm_kernel<<<(ND * 32 + 255) / 256, 256>>>(out_d, 1, l == 0);
    }
}

// round 3
// speedup vs baseline: 2.9659x; 1.4163x over previous
#include <cuda_runtime.h>

#define NM 12000
#define ND 10000
#define DIM 64
#define FEAT 512
#define EMAX 1000000
#define LAYERS 3

// grid constants
#define PROJ_TILE 64
#define GRID_PROJ_M ((NM + PROJ_TILE - 1) / PROJ_TILE)   // 188
#define GRID_PROJ_D ((ND + PROJ_TILE - 1) / PROJ_TILE)   // 157

// ---------------- device scratch ----------------
__device__ float g_memb[NM * DIM];
__device__ float g_demb[ND * DIM];
__device__ float g_pm[NM * DIM];     // W1m @ relu(m_emb) + b1
__device__ float g_pd[ND * DIM];     // W1d @ relu(d_emb)
__device__ float g_rs_m[NM];
__device__ float g_rs_d[ND];
__device__ int   g_off_m[NM + 1];
__device__ int   g_off_d[ND + 1];
__device__ int   g_cur_m[NM];
__device__ int   g_cur_d[ND];
__device__ int   g_col_m[EMAX];
__device__ float g_val_m[EMAX];
__device__ int   g_col_d[EMAX];
__device__ float g_val_d[EMAX];

__device__ __forceinline__ float tanh_fast(float x) {
    float xc = fminf(fmaxf(x, -12.f), 12.f);
    float e2 = __expf(2.f * xc);
    return __fdividef(e2 - 1.f, e2 + 1.f);
}
__device__ __forceinline__ float tanh_approx(float x) {
    float y;
    asm("tanh.approx.f32 %0, %1;" : "=f"(y) : "f"(x));
    return y;
}

// ---------------- init ----------------
__global__ void zero_kernel() {
    int i = blockIdx.x * blockDim.x + threadIdx.x;
    if (i < NM) { g_cur_m[i] = 0; g_rs_m[i] = 0.f; }
    if (i < ND) { g_cur_d[i] = 0; g_rs_d[i] = 0.f; }
}

// ---------------- degree histogram ----------------
__global__ void count_kernel(const int* __restrict__ mi,
                             const int* __restrict__ di, int E) {
    int e = blockIdx.x * blockDim.x + threadIdx.x;
    if (e >= E) return;
    atomicAdd(&g_cur_m[mi[e]], 1);
    atomicAdd(&g_cur_d[di[e]], 1);
}

// ---------------- exclusive scan (block 0: m, block 1: d) ----------------
__global__ void scan_kernel() {
    int which = blockIdx.x;
    int n = which ? ND : NM;
    int* cnt = which ? g_cur_d : g_cur_m;   // in: counts, out: cursors
    int* off = which ? g_off_d : g_off_m;
    __shared__ int part[1024];
    int t = threadIdx.x;
    int chunk = (n + 1023) >> 10;
    int lo = t * chunk;
    int hi = min(n, lo + chunk);
    int s = 0;
    for (int i = lo; i < hi; i++) s += cnt[i];
    part[t] = s;
    __syncthreads();
    for (int dd = 1; dd < 1024; dd <<= 1) {
        int v = (t >= dd) ? part[t - dd] : 0;
        __syncthreads();
        part[t] += v;
        __syncthreads();
    }
    int run = (t == 0) ? 0 : part[t - 1];
    for (int i = lo; i < hi; i++) {
        int c = cnt[i];
        off[i] = run;
        cnt[i] = run;   // scatter cursor
        run += c;
    }
    if (t == 1023) off[n] = part[1023];
}

// ---------------- merged projection GEMM (m and d in one launch) ----------
// tile 64 rows x 64 cols, 256 threads, 4x4 micro-tile, K chunks of 32
__global__ __launch_bounds__(256) void proj_both_kernel(const float* __restrict__ Am,
                                                        const float* __restrict__ Ad,
                                                        const float* __restrict__ Wm,
                                                        const float* __restrict__ Wd) {
    int which = (blockIdx.x >= GRID_PROJ_M) ? 1 : 0;
    int blk = which ? (blockIdx.x - GRID_PROJ_M) : blockIdx.x;
    const float* A = which ? Ad : Am;
    const float* W = which ? Wd : Wm;
    float* C = which ? g_demb : g_memb;
    int Mrows = which ? ND : NM;

    __shared__ float As[PROJ_TILE * 33];
    __shared__ float WsT[32 * 64];
    int tid = threadIdx.x;
    int tx = tid & 15, ty = tid >> 4;
    int row0 = blk * PROJ_TILE;

    float acc[4][4];
#pragma unroll
    for (int i = 0; i < 4; i++)
#pragma unroll
        for (int j = 0; j < 4; j++) acc[i][j] = 0.f;

    for (int kc = 0; kc < FEAT; kc += 32) {
        // A tile: 64 rows x 32 k = 512 float4, 2 per thread
#pragma unroll
        for (int p = 0; p < 2; p++) {
            int idx = p * 256 + tid;
            int r = idx >> 3;
            int kq = idx & 7;
            int grow = row0 + r;
            float4 v = make_float4(0.f, 0.f, 0.f, 0.f);
            if (grow < Mrows)
                v = *(const float4*)(A + (size_t)grow * FEAT + kc + kq * 4);
            float* dst = &As[r * 33 + kq * 4];
            dst[0] = v.x; dst[1] = v.y; dst[2] = v.z; dst[3] = v.w;
        }
        // W tile transposed: 64 cols x 32 k
#pragma unroll
        for (int p = 0; p < 2; p++) {
            int idx = p * 256 + tid;
            int c = idx >> 3;
            int kq = idx & 7;
            float4 v = *(const float4*)(W + (size_t)c * FEAT + kc + kq * 4);
            WsT[(kq * 4 + 0) * 64 + c] = v.x;
            WsT[(kq * 4 + 1) * 64 + c] = v.y;
            WsT[(kq * 4 + 2) * 64 + c] = v.z;
            WsT[(kq * 4 + 3) * 64 + c] = v.w;
        }
        __syncthreads();
#pragma unroll 8
        for (int k = 0; k < 32; k++) {
            float4 w = *(const float4*)&WsT[k * 64 + tx * 4];
#pragma unroll
            for (int i = 0; i < 4; i++) {
                float a = As[(ty * 4 + i) * 33 + k];
                acc[i][0] += a * w.x; acc[i][1] += a * w.y;
                acc[i][2] += a * w.z; acc[i][3] += a * w.w;
            }
        }
        __syncthreads();
    }
#pragma unroll
    for (int i = 0; i < 4; i++) {
        int grow = row0 + ty * 4 + i;
        if (grow < Mrows) {
            float4 v = make_float4(acc[i][0], acc[i][1], acc[i][2], acc[i][3]);
            *(float4*)(C + (size_t)grow * DIM + tx * 4) = v;
        }
    }
}

// ---------------- merged per-node MLP partials (m and d in one launch) -----
// Pm = relu(m_emb) @ W1[:, :64]^T + b1 ; Pd = relu(d_emb) @ W1[:, 64:]^T
__global__ __launch_bounds__(256) void pre_mlp_both_kernel(const float* __restrict__ W1,
                                                           const float* __restrict__ b1) {
    int which = (blockIdx.x >= GRID_PROJ_M) ? 1 : 0;
    int blk = which ? (blockIdx.x - GRID_PROJ_M) : blockIdx.x;
    const float* X = which ? g_demb : g_memb;
    float* P = which ? g_pd : g_pm;
    int Mrows = which ? ND : NM;
    int koff = which ? 64 : 0;

    __shared__ float As[PROJ_TILE * 33];
    __shared__ float WsT[32 * 64];
    int tid = threadIdx.x;
    int tx = tid & 15, ty = tid >> 4;
    int row0 = blk * PROJ_TILE;

    float acc[4][4];
#pragma unroll
    for (int i = 0; i < 4; i++)
#pragma unroll
        for (int j = 0; j < 4; j++) acc[i][j] = 0.f;

    for (int kc = 0; kc < DIM; kc += 32) {
#pragma unroll
        for (int p = 0; p < 2; p++) {
            int idx = p * 256 + tid;
            int r = idx >> 3;
            int kq = idx & 7;
            int grow = row0 + r;
            float4 v = make_float4(0.f, 0.f, 0.f, 0.f);
            if (grow < Mrows)
                v = *(const float4*)(X + (size_t)grow * DIM + kc + kq * 4);
            float* dst = &As[r * 33 + kq * 4];
            dst[0] = fmaxf(v.x, 0.f); dst[1] = fmaxf(v.y, 0.f);
            dst[2] = fmaxf(v.z, 0.f); dst[3] = fmaxf(v.w, 0.f);
        }
#pragma unroll
        for (int p = 0; p < 2; p++) {
            int idx = p * 256 + tid;
            int c = idx >> 3;
            int kq = idx & 7;
            float4 v = *(const float4*)(W1 + (size_t)c * 128 + koff + kc + kq * 4);
            WsT[(kq * 4 + 0) * 64 + c] = v.x;
            WsT[(kq * 4 + 1) * 64 + c] = v.y;
            WsT[(kq * 4 + 2) * 64 + c] = v.z;
            WsT[(kq * 4 + 3) * 64 + c] = v.w;
        }
        __syncthreads();
#pragma unroll 8
        for (int k = 0; k < 32; k++) {
            float4 w = *(const float4*)&WsT[k * 64 + tx * 4];
#pragma unroll
            for (int i = 0; i < 4; i++) {
                float a = As[(ty * 4 + i) * 33 + k];
                acc[i][0] += a * w.x; acc[i][1] += a * w.y;
                acc[i][2] += a * w.z; acc[i][3] += a * w.w;
            }
        }
        __syncthreads();
    }
#pragma unroll
    for (int i = 0; i < 4; i++) {
        int grow = row0 + ty * 4 + i;
        if (grow < Mrows) {
            float4 v = make_float4(acc[i][0], acc[i][1], acc[i][2], acc[i][3]);
            if (!which) {   // fold bias into m-side partial
                float4 bb = *(const float4*)(b1 + tx * 4);
                v.x += bb.x; v.y += bb.y; v.z += bb.z; v.w += bb.w;
            }
            *(float4*)(P + (size_t)grow * DIM + tx * 4) = v;
        }
    }
}

// ---------------- per-edge: gather partials, tanh, dot, exp, scatter CSR ----
__global__ __launch_bounds__(256) void edge_csr_kernel(const float* __restrict__ W2,
                                                       const int* __restrict__ mi,
                                                       const int* __restrict__ di,
                                                       int E) {
    __shared__ float4 sW2[16];
    int tid = threadIdx.x;
    if (tid < 16) sW2[tid] = ((const float4*)W2)[tid];
    __syncthreads();

    int e = blockIdx.x * blockDim.x + tid;
    if (e >= E) return;
    int m = mi[e], d = di[e];

    const float4* pm = (const float4*)(g_pm + (size_t)m * DIM);
    const float4* pd = (const float4*)(g_pd + (size_t)d * DIM);

    float score = 0.f;
#pragma unroll
    for (int q = 0; q < 16; q++) {
        float4 a = pm[q];
        float4 b = pd[q];
        float4 w2 = sW2[q];
        score += tanh_approx(a.x + b.x) * w2.x;
        score += tanh_approx(a.y + b.y) * w2.y;
        score += tanh_approx(a.z + b.z) * w2.z;
        score += tanh_approx(a.w + b.w) * w2.w;
    }
    float w = __expf(score);
    atomicAdd(&g_rs_m[m], w);
    atomicAdd(&g_rs_d[d], w);
    int pmpos = atomicAdd(&g_cur_m[m], 1);
    g_col_m[pmpos] = d; g_val_m[pmpos] = w;
    int pdpos = atomicAdd(&g_cur_d[d], 1);
    g_col_d[pdpos] = m; g_val_d[pdpos] = w;
}

// ---------------- rowsum -> rs^{-0.5} ----------------
__global__ void invnorm_kernel() {
    int i = blockIdx.x * blockDim.x + threadIdx.x;
    if (i < NM) { float r = g_rs_m[i]; g_rs_m[i] = (r > 0.f) ? rsqrtf(r) : 0.f; }
    if (i < ND) { float r = g_rs_d[i]; g_rs_d[i] = (r > 0.f) ? rsqrtf(r) : 0.f; }
}

// ---------------- CSR SpMM + tanh + layer accumulation ----------------
// one warp per row; lane handles 2 of 64 cols; gather unrolled x8 for MLP
__global__ __launch_bounds__(256) void spmm_kernel(float* __restrict__ outacc,
                                                   int dir, int store) {
    const int*   off  = dir ? g_off_d : g_off_m;
    const int*   col  = dir ? g_col_d : g_col_m;
    const float* val  = dir ? g_val_d : g_val_m;
    const float* invn = dir ? g_rs_d : g_rs_m;
    const float* xin  = dir ? g_memb : g_demb;
    float*       xout = dir ? g_demb : g_memb;
    int nrows = dir ? ND : NM;

    int gwarp = (blockIdx.x * blockDim.x + threadIdx.x) >> 5;
    int lane = threadIdx.x & 31;
    if (gwarp >= nrows) return;
    int t = off[gwarp], epos = off[gwarp + 1];

    float a0 = 0.f, a1 = 0.f;
    // unroll-8: broadcast col/val (uniform addr across warp), 8 gathers in flight
    for (; t + 8 <= epos; t += 8) {
        int   c0 = col[t+0], c1 = col[t+1], c2 = col[t+2], c3 = col[t+3];
        int   c4 = col[t+4], c5 = col[t+5], c6 = col[t+6], c7 = col[t+7];
        float v0 = val[t+0], v1 = val[t+1], v2 = val[t+2], v3 = val[t+3];
        float v4 = val[t+4], v5 = val[t+5], v6 = val[t+6], v7 = val[t+7];
        float2 x0 = *(const float2*)(xin + (size_t)c0 * DIM + lane * 2);
        float2 x1 = *(const float2*)(xin + (size_t)c1 * DIM + lane * 2);
        float2 x2 = *(const float2*)(xin + (size_t)c2 * DIM + lane * 2);
        float2 x3 = *(const float2*)(xin + (size_t)c3 * DIM + lane * 2);
        float2 x4 = *(const float2*)(xin + (size_t)c4 * DIM + lane * 2);
        float2 x5 = *(const float2*)(xin + (size_t)c5 * DIM + lane * 2);
        float2 x6 = *(const float2*)(xin + (size_t)c6 * DIM + lane * 2);
        float2 x7 = *(const float2*)(xin + (size_t)c7 * DIM + lane * 2);
        a0 += v0 * x0.x; a1 += v0 * x0.y;
        a0 += v1 * x1.x; a1 += v1 * x1.y;
        a0 += v2 * x2.x; a1 += v2 * x2.y;
        a0 += v3 * x3.x; a1 += v3 * x3.y;
        a0 += v4 * x4.x; a1 += v4 * x4.y;
        a0 += v5 * x5.x; a1 += v5 * x5.y;
        a0 += v6 * x6.x; a1 += v6 * x6.y;
        a0 += v7 * x7.x; a1 += v7 * x7.y;
    }
    for (; t < epos; t++) {
        int c = col[t]; float v = val[t];
        float2 x = *(const float2*)(xin + (size_t)c * DIM + lane * 2);
        a0 += v * x.x; a1 += v * x.y;
    }
    float inv = invn[gwarp];
    float y0 = tanh_fast(a0 * inv);
    float y1 = tanh_fast(a1 * inv);
    float* xo = xout + (size_t)gwarp * DIM + lane * 2;
    xo[0] = y0; xo[1] = y1;
    float* oa = outacc + (size_t)gwarp * DIM + lane * 2;
    if (store) { oa[0] = y0; oa[1] = y1; }
    else       { oa[0] += y0; oa[1] += y1; }
}

// ---------------- launch ----------------
extern "C" void kernel_launch(void* const* d_in, const int* in_sizes, int n_in,
                              void* d_out, int out_size) {
    const float* m_sim = (const float*)d_in[0];
    const float* d_sim = (const float*)d_in[1];
    const float* Wm    = (const float*)d_in[2];
    const float* Wd    = (const float*)d_in[3];
    const float* W1    = (const float*)d_in[4];
    const float* b1    = (const float*)d_in[5];
    const float* W2    = (const float*)d_in[6];
    const int*   mi    = (const int*)d_in[7];
    const int*   di    = (const int*)d_in[8];
    int E = in_sizes[7];
    float* out = (float*)d_out;

    zero_kernel<<<(NM + 255) / 256, 256>>>();
    count_kernel<<<(E + 255) / 256, 256>>>(mi, di, E);
    scan_kernel<<<2, 1024>>>();
    proj_both_kernel<<<GRID_PROJ_M + GRID_PROJ_D, 256>>>(m_sim, d_sim, Wm, Wd);
    pre_mlp_both_kernel<<<GRID_PROJ_M + GRID_PROJ_D, 256>>>(W1, b1);
    edge_csr_kernel<<<(E + 255) / 256, 256>>>(W2, mi, di, E);
    invnorm_kernel<<<(NM + 255) / 256, 256>>>();

    float* out_m = out;
    float* out_d = out + (size_t)NM * DIM;
    for (int l = 0; l < LAYERS; l++) {
        spmm_kernel<<<(NM * 32 + 255) / 256, 256>>>(out_m, 0, l == 0);
        spmm_kernel<<<(ND * 32 + 255) / 256, 256>>>(out_d, 1, l == 0);
    }
}

// round 7
// speedup vs baseline: 3.4119x; 1.1504x over previous
#include <cuda_runtime.h>
#include <cuda_fp16.h>

#define NM 12000
#define ND 10000
#define DIM 64
#define FEAT 512
#define EMAX 1000000
#define LAYERS 3

#define PROJ_TILE 64
#define GRID_PROJ_M ((NM + PROJ_TILE - 1) / PROJ_TILE)   // 188
#define GRID_PROJ_D ((ND + PROJ_TILE - 1) / PROJ_TILE)   // 157
#define GRID_PB (GRID_PROJ_M + GRID_PROJ_D)              // 345

// ---------------- device scratch ----------------
__device__ float   g_memb[NM * DIM];
__device__ float   g_demb[ND * DIM];
__device__ float   g_pm[NM * DIM];      // split-K partial (temp)
__device__ float   g_pd[ND * DIM];      // split-K partial (temp)
__device__ __half2 g_membh[NM * DIM / 2];   // half mirror of embeddings
__device__ __half2 g_dembh[ND * DIM / 2];
__device__ __half2 g_pmh[NM * DIM / 2];     // half MLP partials (+b1 on m side)
__device__ __half2 g_pdh[ND * DIM / 2];
__device__ float   g_rs_m[NM];
__device__ float   g_rs_d[ND];
__device__ int     g_off_m[NM + 1];
__device__ int     g_off_d[ND + 1];
__device__ int     g_cur_m[NM];
__device__ int     g_cur_d[ND];
__device__ int     g_col_m[EMAX];
__device__ float   g_val_m[EMAX];
__device__ int     g_col_d[EMAX];
__device__ float   g_val_d[EMAX];

__device__ __forceinline__ float tanh_fast(float x) {
    float xc = fminf(fmaxf(x, -12.f), 12.f);
    float e2 = __expf(2.f * xc);
    return __fdividef(e2 - 1.f, e2 + 1.f);
}
__device__ __forceinline__ float tanh_approx(float x) {
    float y;
    asm("tanh.approx.f32 %0, %1;" : "=f"(y) : "f"(x));
    return y;
}

// ---------------- init ----------------
__global__ void zero_kernel() {
    int i = blockIdx.x * blockDim.x + threadIdx.x;
    if (i < NM) g_cur_m[i] = 0;
    if (i < ND) g_cur_d[i] = 0;
}

// ---------------- degree histogram ----------------
__global__ void count_kernel(const int* __restrict__ mi,
                             const int* __restrict__ di, int E) {
    int e = blockIdx.x * blockDim.x + threadIdx.x;
    if (e >= E) return;
    atomicAdd(&g_cur_m[mi[e]], 1);
    atomicAdd(&g_cur_d[di[e]], 1);
}

// ---------------- exclusive scan (block 0: m, block 1: d) ----------------
__global__ void scan_kernel() {
    int which = blockIdx.x;
    int n = which ? ND : NM;
    int* cnt = which ? g_cur_d : g_cur_m;
    int* off = which ? g_off_d : g_off_m;
    __shared__ int part[1024];
    int t = threadIdx.x;
    int chunk = (n + 1023) >> 10;
    int lo = t * chunk;
    int hi = min(n, lo + chunk);
    int s = 0;
    for (int i = lo; i < hi; i++) s += cnt[i];
    part[t] = s;
    __syncthreads();
    for (int dd = 1; dd < 1024; dd <<= 1) {
        int v = (t >= dd) ? part[t - dd] : 0;
        __syncthreads();
        part[t] += v;
        __syncthreads();
    }
    int run = (t == 0) ? 0 : part[t - 1];
    for (int i = lo; i < hi; i++) {
        int c = cnt[i];
        off[i] = run;
        cnt[i] = run;   // scatter cursor
        run += c;
    }
    if (t == 1023) off[n] = part[1023];
}

// ---------------- projection GEMM, split-K x2, m+d merged -----------------
// khalf 0 -> g_memb/g_demb ; khalf 1 -> g_pm/g_pd (combined later)
__global__ __launch_bounds__(256) void proj_both_kernel(const float* __restrict__ Am,
                                                        const float* __restrict__ Ad,
                                                        const float* __restrict__ Wm,
                                                        const float* __restrict__ Wd) {
    int bid = blockIdx.x;
    int khalf = (bid >= GRID_PB) ? 1 : 0;
    int rem = khalf ? bid - GRID_PB : bid;
    int which = (rem >= GRID_PROJ_M) ? 1 : 0;
    int blk = which ? (rem - GRID_PROJ_M) : rem;
    const float* A = which ? Ad : Am;
    const float* W = which ? Wd : Wm;
    float* C = khalf ? (which ? g_pd : g_pm) : (which ? g_demb : g_memb);
    int Mrows = which ? ND : NM;
    int kbase = khalf * (FEAT / 2);

    __shared__ float As[PROJ_TILE * 33];
    __shared__ float WsT[32 * 64];
    int tid = threadIdx.x;
    int tx = tid & 15, ty = tid >> 4;
    int row0 = blk * PROJ_TILE;

    float acc[4][4];
#pragma unroll
    for (int i = 0; i < 4; i++)
#pragma unroll
        for (int j = 0; j < 4; j++) acc[i][j] = 0.f;

    for (int kc = kbase; kc < kbase + FEAT / 2; kc += 32) {
#pragma unroll
        for (int p = 0; p < 2; p++) {
            int idx = p * 256 + tid;
            int r = idx >> 3;
            int kq = idx & 7;
            int grow = row0 + r;
            float4 v = make_float4(0.f, 0.f, 0.f, 0.f);
            if (grow < Mrows)
                v = *(const float4*)(A + (size_t)grow * FEAT + kc + kq * 4);
            float* dst = &As[r * 33 + kq * 4];
            dst[0] = v.x; dst[1] = v.y; dst[2] = v.z; dst[3] = v.w;
        }
#pragma unroll
        for (int p = 0; p < 2; p++) {
            int idx = p * 256 + tid;
            int c = idx >> 3;
            int kq = idx & 7;
            float4 v = *(const float4*)(W + (size_t)c * FEAT + kc + kq * 4);
            WsT[(kq * 4 + 0) * 64 + c] = v.x;
            WsT[(kq * 4 + 1) * 64 + c] = v.y;
            WsT[(kq * 4 + 2) * 64 + c] = v.z;
            WsT[(kq * 4 + 3) * 64 + c] = v.w;
        }
        __syncthreads();
#pragma unroll 8
        for (int k = 0; k < 32; k++) {
            float4 w = *(const float4*)&WsT[k * 64 + tx * 4];
#pragma unroll
            for (int i = 0; i < 4; i++) {
                float a = As[(ty * 4 + i) * 33 + k];
                acc[i][0] += a * w.x; acc[i][1] += a * w.y;
                acc[i][2] += a * w.z; acc[i][3] += a * w.w;
            }
        }
        __syncthreads();
    }
#pragma unroll
    for (int i = 0; i < 4; i++) {
        int grow = row0 + ty * 4 + i;
        if (grow < Mrows) {
            float4 v = make_float4(acc[i][0], acc[i][1], acc[i][2], acc[i][3]);
            *(float4*)(C + (size_t)grow * DIM + tx * 4) = v;
        }
    }
}

// ---------------- combine split-K halves + build half mirror --------------
__global__ void combine_kernel() {
    int i = blockIdx.x * blockDim.x + threadIdx.x;  // half2 index
    int totm = NM * DIM / 2;
    int totd = ND * DIM / 2;
    if (i < totm) {
        float2 a = *(const float2*)(g_memb + 2 * i);
        float2 b = *(const float2*)(g_pm + 2 * i);
        float2 s = make_float2(a.x + b.x, a.y + b.y);
        *(float2*)(g_memb + 2 * i) = s;
        g_membh[i] = __float22half2_rn(s);
    } else if (i < totm + totd) {
        int j = i - totm;
        float2 a = *(const float2*)(g_demb + 2 * j);
        float2 b = *(const float2*)(g_pd + 2 * j);
        float2 s = make_float2(a.x + b.x, a.y + b.y);
        *(float2*)(g_demb + 2 * j) = s;
        g_dembh[j] = __float22half2_rn(s);
    }
}

// ---------------- per-node MLP partials -> half2 (m and d merged) ---------
__global__ __launch_bounds__(256) void pre_mlp_both_kernel(const float* __restrict__ W1,
                                                           const float* __restrict__ b1) {
    int which = (blockIdx.x >= GRID_PROJ_M) ? 1 : 0;
    int blk = which ? (blockIdx.x - GRID_PROJ_M) : blockIdx.x;
    const float* X = which ? g_demb : g_memb;
    __half2* P = which ? g_pdh : g_pmh;
    int Mrows = which ? ND : NM;
    int koff = which ? 64 : 0;

    __shared__ float As[PROJ_TILE * 33];
    __shared__ float WsT[32 * 64];
    int tid = threadIdx.x;
    int tx = tid & 15, ty = tid >> 4;
    int row0 = blk * PROJ_TILE;

    float acc[4][4];
#pragma unroll
    for (int i = 0; i < 4; i++)
#pragma unroll
        for (int j = 0; j < 4; j++) acc[i][j] = 0.f;

    for (int kc = 0; kc < DIM; kc += 32) {
#pragma unroll
        for (int p = 0; p < 2; p++) {
            int idx = p * 256 + tid;
            int r = idx >> 3;
            int kq = idx & 7;
            int grow = row0 + r;
            float4 v = make_float4(0.f, 0.f, 0.f, 0.f);
            if (grow < Mrows)
                v = *(const float4*)(X + (size_t)grow * DIM + kc + kq * 4);
            float* dst = &As[r * 33 + kq * 4];
            dst[0] = fmaxf(v.x, 0.f); dst[1] = fmaxf(v.y, 0.f);
            dst[2] = fmaxf(v.z, 0.f); dst[3] = fmaxf(v.w, 0.f);
        }
#pragma unroll
        for (int p = 0; p < 2; p++) {
            int idx = p * 256 + tid;
            int c = idx >> 3;
            int kq = idx & 7;
            float4 v = *(const float4*)(W1 + (size_t)c * 128 + koff + kc + kq * 4);
            WsT[(kq * 4 + 0) * 64 + c] = v.x;
            WsT[(kq * 4 + 1) * 64 + c] = v.y;
            WsT[(kq * 4 + 2) * 64 + c] = v.z;
            WsT[(kq * 4 + 3) * 64 + c] = v.w;
        }
        __syncthreads();
#pragma unroll 8
        for (int k = 0; k < 32; k++) {
            float4 w = *(const float4*)&WsT[k * 64 + tx * 4];
#pragma unroll
            for (int i = 0; i < 4; i++) {
                float a = As[(ty * 4 + i) * 33 + k];
                acc[i][0] += a * w.x; acc[i][1] += a * w.y;
                acc[i][2] += a * w.z; acc[i][3] += a * w.w;
            }
        }
        __syncthreads();
    }
#pragma unroll
    for (int i = 0; i < 4; i++) {
        int grow = row0 + ty * 4 + i;
        if (grow < Mrows) {
            float4 v = make_float4(acc[i][0], acc[i][1], acc[i][2], acc[i][3]);
            if (!which) {   // fold bias into m-side partial
                float4 bb = *(const float4*)(b1 + tx * 4);
                v.x += bb.x; v.y += bb.y; v.z += bb.z; v.w += bb.w;
            }
            P[(size_t)grow * 32 + tx * 2 + 0] = __float22half2_rn(make_float2(v.x, v.y));
            P[(size_t)grow * 32 + tx * 2 + 1] = __float22half2_rn(make_float2(v.z, v.w));
        }
    }
}

// ---------------- per-edge: gather half partials, tanh, dot, exp, scatter --
// row = 64 halfs = 32 half2 = 8 uint4 (FIXED: was 4, dropping half the units)
__global__ __launch_bounds__(256) void edge_csr_kernel(const float* __restrict__ W2,
                                                       const int* __restrict__ mi,
                                                       const int* __restrict__ di,
                                                       int E) {
    __shared__ float sW2[64];
    int tid = threadIdx.x;
    if (tid < 64) sW2[tid] = W2[tid];
    __syncthreads();

    int e = blockIdx.x * blockDim.x + tid;
    if (e >= E) return;
    int m = mi[e], d = di[e];

    const uint4* pm = (const uint4*)(g_pmh + (size_t)m * 32);  // 8 x uint4 per row
    const uint4* pd = (const uint4*)(g_pdh + (size_t)d * 32);

    float score = 0.f;
#pragma unroll
    for (int q = 0; q < 8; q++) {
        uint4 ua = pm[q];
        uint4 ub = pd[q];
        const unsigned* ap = (const unsigned*)&ua;
        const unsigned* bp = (const unsigned*)&ub;
#pragma unroll
        for (int s = 0; s < 4; s++) {
            float2 fa = __half22float2(*(const __half2*)&ap[s]);
            float2 fb = __half22float2(*(const __half2*)&bp[s]);
            int j = q * 8 + s * 2;
            score += tanh_approx(fa.x + fb.x) * sW2[j + 0];
            score += tanh_approx(fa.y + fb.y) * sW2[j + 1];
        }
    }
    float w = __expf(score);
    int pmpos = atomicAdd(&g_cur_m[m], 1);
    g_col_m[pmpos] = d; g_val_m[pmpos] = w;
    int pdpos = atomicAdd(&g_cur_d[d], 1);
    g_col_d[pdpos] = m; g_val_d[pdpos] = w;
}

// ---------------- row sums from CSR vals -> rs^{-0.5} (warp per row) ------
__global__ __launch_bounds__(256) void invnorm_kernel() {
    int gw = (blockIdx.x * blockDim.x + threadIdx.x) >> 5;
    int lane = threadIdx.x & 31;
    if (gw >= NM + ND) return;
    int dir = (gw >= NM) ? 1 : 0;
    int row = dir ? gw - NM : gw;
    const int* off = dir ? g_off_d : g_off_m;
    const float* val = dir ? g_val_d : g_val_m;
    int s = off[row], e = off[row + 1];
    float sum = 0.f;
    for (int t = s + lane; t < e; t += 32) sum += val[t];
#pragma unroll
    for (int o = 16; o > 0; o >>= 1) sum += __shfl_down_sync(0xffffffffu, sum, o);
    if (lane == 0) {
        float r = (sum > 0.f) ? rsqrtf(sum) : 0.f;
        if (dir) g_rs_d[row] = r; else g_rs_m[row] = r;
    }
}

// ---------------- CSR SpMM (half gathers) + tanh + accumulation -----------
// one warp per row; lane handles one half2 (2 of 64 cols)
__global__ __launch_bounds__(256) void spmm_kernel(float* __restrict__ outacc,
                                                   int dir, int store) {
    const int*     off  = dir ? g_off_d : g_off_m;
    const int*     col  = dir ? g_col_d : g_col_m;
    const float*   val  = dir ? g_val_d : g_val_m;
    const float*   invn = dir ? g_rs_d : g_rs_m;
    const __half2* xin  = dir ? g_membh : g_dembh;
    __half2*       xout = dir ? g_dembh : g_membh;
    int nrows = dir ? ND : NM;

    int gwarp = (blockIdx.x * blockDim.x + threadIdx.x) >> 5;
    int lane = threadIdx.x & 31;
    if (gwarp >= nrows) return;
    int t = off[gwarp], epos = off[gwarp + 1];

    float a0 = 0.f, a1 = 0.f;
    for (; t + 8 <= epos; t += 8) {
        int   c0 = col[t+0], c1 = col[t+1], c2 = col[t+2], c3 = col[t+3];
        int   c4 = col[t+4], c5 = col[t+5], c6 = col[t+6], c7 = col[t+7];
        float v0 = val[t+0], v1 = val[t+1], v2 = val[t+2], v3 = val[t+3];
        float v4 = val[t+4], v5 = val[t+5], v6 = val[t+6], v7 = val[t+7];
        __half2 x0 = xin[(size_t)c0 * 32 + lane];
        __half2 x1 = xin[(size_t)c1 * 32 + lane];
        __half2 x2 = xin[(size_t)c2 * 32 + lane];
        __half2 x3 = xin[(size_t)c3 * 32 + lane];
        __half2 x4 = xin[(size_t)c4 * 32 + lane];
        __half2 x5 = xin[(size_t)c5 * 32 + lane];
        __half2 x6 = xin[(size_t)c6 * 32 + lane];
        __half2 x7 = xin[(size_t)c7 * 32 + lane];
        float2 f;
        f = __half22float2(x0); a0 += v0 * f.x; a1 += v0 * f.y;
        f = __half22float2(x1); a0 += v1 * f.x; a1 += v1 * f.y;
        f = __half22float2(x2); a0 += v2 * f.x; a1 += v2 * f.y;
        f = __half22float2(x3); a0 += v3 * f.x; a1 += v3 * f.y;
        f = __half22float2(x4); a0 += v4 * f.x; a1 += v4 * f.y;
        f = __half22float2(x5); a0 += v5 * f.x; a1 += v5 * f.y;
        f = __half22float2(x6); a0 += v6 * f.x; a1 += v6 * f.y;
        f = __half22float2(x7); a0 += v7 * f.x; a1 += v7 * f.y;
    }
    for (; t < epos; t++) {
        int c = col[t]; float v = val[t];
        float2 f = __half22float2(xin[(size_t)c * 32 + lane]);
        a0 += v * f.x; a1 += v * f.y;
    }
    float inv = invn[gwarp];
    float y0 = tanh_fast(a0 * inv);
    float y1 = tanh_fast(a1 * inv);
    xout[(size_t)gwarp * 32 + lane] = __float22half2_rn(make_float2(y0, y1));
    float* oa = outacc + (size_t)gwarp * DIM + lane * 2;
    if (store) { oa[0] = y0; oa[1] = y1; }
    else       { oa[0] += y0; oa[1] += y1; }
}

// ---------------- launch ----------------
extern "C" void kernel_launch(void* const* d_in, const int* in_sizes, int n_in,
                              void* d_out, int out_size) {
    const float* m_sim = (const float*)d_in[0];
    const float* d_sim = (const float*)d_in[1];
    const float* Wm    = (const float*)d_in[2];
    const float* Wd    = (const float*)d_in[3];
    const float* W1    = (const float*)d_in[4];
    const float* b1    = (const float*)d_in[5];
    const float* W2    = (const float*)d_in[6];
    const int*   mi    = (const int*)d_in[7];
    const int*   di    = (const int*)d_in[8];
    int E = in_sizes[7];
    float* out = (float*)d_out;

    zero_kernel<<<(NM + 255) / 256, 256>>>();
    count_kernel<<<(E + 255) / 256, 256>>>(mi, di, E);
    proj_both_kernel<<<2 * GRID_PB, 256>>>(m_sim, d_sim, Wm, Wd);
    scan_kernel<<<2, 1024>>>();
    combine_kernel<<<((NM + ND) * DIM / 2 + 255) / 256, 256>>>();
    pre_mlp_both_kernel<<<GRID_PB, 256>>>(W1, b1);
    edge_csr_kernel<<<(E + 255) / 256, 256>>>(W2, mi, di, E);
    invnorm_kernel<<<((NM + ND) * 32 + 255) / 256, 256>>>();

    float* out_m = out;
    float* out_d = out + (size_t)NM * DIM;
    for (int l = 0; l < LAYERS; l++) {
        spmm_kernel<<<(NM * 32 + 255) / 256, 256>>>(out_m, 0, l == 0);
        spmm_kernel<<<(ND * 32 + 255) / 256, 256>>>(out_d, 1, l == 0);
    }
}

// round 8
// speedup vs baseline: 3.7304x; 1.0934x over previous
#include <cuda_runtime.h>
#include <cuda_fp16.h>

#define NM 12000
#define ND 10000
#define DIM 64
#define FEAT 512
#define EMAX 1000000
#define EPAD 1100000          // EMAX + worst-case 8-alignment padding (<= 96000)
#define LAYERS 3

#define PROJ_TILE 64
#define GRID_PROJ_M ((NM + PROJ_TILE - 1) / PROJ_TILE)   // 188
#define GRID_PROJ_D ((ND + PROJ_TILE - 1) / PROJ_TILE)   // 157
#define GRID_PB (GRID_PROJ_M + GRID_PROJ_D)              // 345
#define NCOUNT 512            // histogram blocks fused into proj launch

// ---------------- device scratch ----------------
__device__ float   g_memb[NM * DIM];
__device__ float   g_demb[ND * DIM];
__device__ float   g_pm[NM * DIM];      // split-K partial (temp)
__device__ float   g_pd[ND * DIM];      // split-K partial (temp)
__device__ __half2 g_membh[NM * DIM / 2];   // half mirror of embeddings
__device__ __half2 g_dembh[ND * DIM / 2];
__device__ __half2 g_pmh[NM * DIM / 2];     // half MLP partials (+b1 on m side)
__device__ __half2 g_pdh[ND * DIM / 2];
__device__ float   g_rs_m[NM];
__device__ float   g_rs_d[ND];
__device__ int     g_off_m[NM];         // 8-aligned row starts
__device__ int     g_off_d[ND];
__device__ int     g_cur_m[NM];         // counts -> cursors -> row ends
__device__ int     g_cur_d[ND];
__device__ int     g_col_m[EPAD];
__device__ float   g_val_m[EPAD];
__device__ int     g_col_d[EPAD];
__device__ float   g_val_d[EPAD];

__device__ __forceinline__ float tanh_fast(float x) {
    float xc = fminf(fmaxf(x, -12.f), 12.f);
    float e2 = __expf(2.f * xc);
    return __fdividef(e2 - 1.f, e2 + 1.f);
}
__device__ __forceinline__ float tanh_approx(float x) {
    float y;
    asm("tanh.approx.f32 %0, %1;" : "=f"(y) : "f"(x));
    return y;
}

// ---------------- init ----------------
__global__ void zero_kernel() {
    int i = blockIdx.x * blockDim.x + threadIdx.x;
    if (i < NM) g_cur_m[i] = 0;
    if (i < ND) g_cur_d[i] = 0;
}

// ---------------- projection GEMM (split-K x2, m+d) + fused count ---------
// blocks [0, 2*GRID_PB): proj ; blocks [2*GRID_PB, +NCOUNT): edge histogram
__global__ __launch_bounds__(256) void proj_count_kernel(const float* __restrict__ Am,
                                                         const float* __restrict__ Ad,
                                                         const float* __restrict__ Wm,
                                                         const float* __restrict__ Wd,
                                                         const int* __restrict__ mi,
                                                         const int* __restrict__ di,
                                                         int E) {
    __shared__ float As[PROJ_TILE * 33];
    __shared__ float WsT[32 * 64];
    int tid = threadIdx.x;
    int bid = blockIdx.x;

    if (bid >= 2 * GRID_PB) {
        // -------- histogram part --------
        int b = bid - 2 * GRID_PB;
        for (int e = b * 256 + tid; e < E; e += NCOUNT * 256) {
            atomicAdd(&g_cur_m[mi[e]], 1);
            atomicAdd(&g_cur_d[di[e]], 1);
        }
        return;
    }

    // -------- projection part --------
    int khalf = (bid >= GRID_PB) ? 1 : 0;
    int rem = khalf ? bid - GRID_PB : bid;
    int which = (rem >= GRID_PROJ_M) ? 1 : 0;
    int blk = which ? (rem - GRID_PROJ_M) : rem;
    const float* A = which ? Ad : Am;
    const float* W = which ? Wd : Wm;
    float* C = khalf ? (which ? g_pd : g_pm) : (which ? g_demb : g_memb);
    int Mrows = which ? ND : NM;
    int kbase = khalf * (FEAT / 2);

    int tx = tid & 15, ty = tid >> 4;
    int row0 = blk * PROJ_TILE;

    float acc[4][4];
#pragma unroll
    for (int i = 0; i < 4; i++)
#pragma unroll
        for (int j = 0; j < 4; j++) acc[i][j] = 0.f;

    for (int kc = kbase; kc < kbase + FEAT / 2; kc += 32) {
#pragma unroll
        for (int p = 0; p < 2; p++) {
            int idx = p * 256 + tid;
            int r = idx >> 3;
            int kq = idx & 7;
            int grow = row0 + r;
            float4 v = make_float4(0.f, 0.f, 0.f, 0.f);
            if (grow < Mrows)
                v = *(const float4*)(A + (size_t)grow * FEAT + kc + kq * 4);
            float* dst = &As[r * 33 + kq * 4];
            dst[0] = v.x; dst[1] = v.y; dst[2] = v.z; dst[3] = v.w;
        }
#pragma unroll
        for (int p = 0; p < 2; p++) {
            int idx = p * 256 + tid;
            int c = idx >> 3;
            int kq = idx & 7;
            float4 v = *(const float4*)(W + (size_t)c * FEAT + kc + kq * 4);
            WsT[(kq * 4 + 0) * 64 + c] = v.x;
            WsT[(kq * 4 + 1) * 64 + c] = v.y;
            WsT[(kq * 4 + 2) * 64 + c] = v.z;
            WsT[(kq * 4 + 3) * 64 + c] = v.w;
        }
        __syncthreads();
#pragma unroll 8
        for (int k = 0; k < 32; k++) {
            float4 w = *(const float4*)&WsT[k * 64 + tx * 4];
#pragma unroll
            for (int i = 0; i < 4; i++) {
                float a = As[(ty * 4 + i) * 33 + k];
                acc[i][0] += a * w.x; acc[i][1] += a * w.y;
                acc[i][2] += a * w.z; acc[i][3] += a * w.w;
            }
        }
        __syncthreads();
    }
#pragma unroll
    for (int i = 0; i < 4; i++) {
        int grow = row0 + ty * 4 + i;
        if (grow < Mrows) {
            float4 v = make_float4(acc[i][0], acc[i][1], acc[i][2], acc[i][3]);
            *(float4*)(C + (size_t)grow * DIM + tx * 4) = v;
        }
    }
}

// ---------------- exclusive scan with 8-alignment padding -----------------
// block 0: m-side, block 1: d-side. Each active thread handles 16 counts
// via int4 loads/stores. Offsets are cumulative CEIL8(count).
__global__ void scan_kernel() {
    int which = blockIdx.x;
    int n = which ? ND : NM;                 // both divisible by 16
    int* cnt = which ? g_cur_d : g_cur_m;    // in: counts, out: cursors(starts)
    int* off = which ? g_off_d : g_off_m;
    __shared__ int part[1024];
    int t = threadIdx.x;
    int nth = n >> 4;
    int base = t << 4;

    int4 c[4];
    int s = 0;
    if (t < nth) {
#pragma unroll
        for (int q = 0; q < 4; q++)
            c[q] = *(const int4*)(cnt + base + q * 4);
        const int* cp = (const int*)c;
#pragma unroll
        for (int q = 0; q < 16; q++) s += (cp[q] + 7) & ~7;
    }
    part[t] = s;
    __syncthreads();
    for (int dd = 1; dd < 1024; dd <<= 1) {
        int v = (t >= dd) ? part[t - dd] : 0;
        __syncthreads();
        part[t] += v;
        __syncthreads();
    }
    if (t < nth) {
        int run = (t == 0) ? 0 : part[t - 1];
        const int* cp = (const int*)c;
        int o[16];
#pragma unroll
        for (int q = 0; q < 16; q++) { o[q] = run; run += (cp[q] + 7) & ~7; }
#pragma unroll
        for (int q = 0; q < 4; q++) {
            *(int4*)(off + base + q * 4) = ((const int4*)o)[q];
            *(int4*)(cnt + base + q * 4) = ((const int4*)o)[q];
        }
    }
}

// ---------------- combine split-K halves + build half mirror --------------
__global__ void combine_kernel() {
    int i = blockIdx.x * blockDim.x + threadIdx.x;  // half2 index
    int totm = NM * DIM / 2;
    int totd = ND * DIM / 2;
    if (i < totm) {
        float2 a = *(const float2*)(g_memb + 2 * i);
        float2 b = *(const float2*)(g_pm + 2 * i);
        float2 s = make_float2(a.x + b.x, a.y + b.y);
        *(float2*)(g_memb + 2 * i) = s;
        g_membh[i] = __float22half2_rn(s);
    } else if (i < totm + totd) {
        int j = i - totm;
        float2 a = *(const float2*)(g_demb + 2 * j);
        float2 b = *(const float2*)(g_pd + 2 * j);
        float2 s = make_float2(a.x + b.x, a.y + b.y);
        *(float2*)(g_demb + 2 * j) = s;
        g_dembh[j] = __float22half2_rn(s);
    }
}

// ---------------- per-node MLP partials -> half2 (m and d merged) ---------
__global__ __launch_bounds__(256) void pre_mlp_both_kernel(const float* __restrict__ W1,
                                                           const float* __restrict__ b1) {
    int which = (blockIdx.x >= GRID_PROJ_M) ? 1 : 0;
    int blk = which ? (blockIdx.x - GRID_PROJ_M) : blockIdx.x;
    const float* X = which ? g_demb : g_memb;
    __half2* P = which ? g_pdh : g_pmh;
    int Mrows = which ? ND : NM;
    int koff = which ? 64 : 0;

    __shared__ float As[PROJ_TILE * 33];
    __shared__ float WsT[32 * 64];
    int tid = threadIdx.x;
    int tx = tid & 15, ty = tid >> 4;
    int row0 = blk * PROJ_TILE;

    float acc[4][4];
#pragma unroll
    for (int i = 0; i < 4; i++)
#pragma unroll
        for (int j = 0; j < 4; j++) acc[i][j] = 0.f;

    for (int kc = 0; kc < DIM; kc += 32) {
#pragma unroll
        for (int p = 0; p < 2; p++) {
            int idx = p * 256 + tid;
            int r = idx >> 3;
            int kq = idx & 7;
            int grow = row0 + r;
            float4 v = make_float4(0.f, 0.f, 0.f, 0.f);
            if (grow < Mrows)
                v = *(const float4*)(X + (size_t)grow * DIM + kc + kq * 4);
            float* dst = &As[r * 33 + kq * 4];
            dst[0] = fmaxf(v.x, 0.f); dst[1] = fmaxf(v.y, 0.f);
            dst[2] = fmaxf(v.z, 0.f); dst[3] = fmaxf(v.w, 0.f);
        }
#pragma unroll
        for (int p = 0; p < 2; p++) {
            int idx = p * 256 + tid;
            int c = idx >> 3;
            int kq = idx & 7;
            float4 v = *(const float4*)(W1 + (size_t)c * 128 + koff + kc + kq * 4);
            WsT[(kq * 4 + 0) * 64 + c] = v.x;
            WsT[(kq * 4 + 1) * 64 + c] = v.y;
            WsT[(kq * 4 + 2) * 64 + c] = v.z;
            WsT[(kq * 4 + 3) * 64 + c] = v.w;
        }
        __syncthreads();
#pragma unroll 8
        for (int k = 0; k < 32; k++) {
            float4 w = *(const float4*)&WsT[k * 64 + tx * 4];
#pragma unroll
            for (int i = 0; i < 4; i++) {
                float a = As[(ty * 4 + i) * 33 + k];
                acc[i][0] += a * w.x; acc[i][1] += a * w.y;
                acc[i][2] += a * w.z; acc[i][3] += a * w.w;
            }
        }
        __syncthreads();
    }
#pragma unroll
    for (int i = 0; i < 4; i++) {
        int grow = row0 + ty * 4 + i;
        if (grow < Mrows) {
            float4 v = make_float4(acc[i][0], acc[i][1], acc[i][2], acc[i][3]);
            if (!which) {   // fold bias into m-side partial
                float4 bb = *(const float4*)(b1 + tx * 4);
                v.x += bb.x; v.y += bb.y; v.z += bb.z; v.w += bb.w;
            }
            P[(size_t)grow * 32 + tx * 2 + 0] = __float22half2_rn(make_float2(v.x, v.y));
            P[(size_t)grow * 32 + tx * 2 + 1] = __float22half2_rn(make_float2(v.z, v.w));
        }
    }
}

// ---------------- per-edge: gather half partials, tanh, dot, exp, scatter --
__global__ __launch_bounds__(256) void edge_csr_kernel(const float* __restrict__ W2,
                                                       const int* __restrict__ mi,
                                                       const int* __restrict__ di,
                                                       int E) {
    __shared__ float sW2[64];
    int tid = threadIdx.x;
    if (tid < 64) sW2[tid] = W2[tid];
    __syncthreads();

    int e = blockIdx.x * blockDim.x + tid;
    if (e >= E) return;
    int m = mi[e], d = di[e];

    const uint4* pm = (const uint4*)(g_pmh + (size_t)m * 32);  // 8 x uint4 per row
    const uint4* pd = (const uint4*)(g_pdh + (size_t)d * 32);

    float score = 0.f;
#pragma unroll
    for (int q = 0; q < 8; q++) {
        uint4 ua = pm[q];
        uint4 ub = pd[q];
        const unsigned* ap = (const unsigned*)&ua;
        const unsigned* bp = (const unsigned*)&ub;
#pragma unroll
        for (int s = 0; s < 4; s++) {
            float2 fa = __half22float2(*(const __half2*)&ap[s]);
            float2 fb = __half22float2(*(const __half2*)&bp[s]);
            int j = q * 8 + s * 2;
            score += tanh_approx(fa.x + fb.x) * sW2[j + 0];
            score += tanh_approx(fa.y + fb.y) * sW2[j + 1];
        }
    }
    float w = __expf(score);
    int pmpos = atomicAdd(&g_cur_m[m], 1);
    g_col_m[pmpos] = d; g_val_m[pmpos] = w;
    int pdpos = atomicAdd(&g_cur_d[d], 1);
    g_col_d[pdpos] = m; g_val_d[pdpos] = w;
}

// ---------------- row sums from CSR vals -> rs^{-0.5} (warp per row) ------
// row range = [off[row], cur[row])  (cur = end cursor after scatter)
__global__ __launch_bounds__(256) void invnorm_kernel() {
    int gw = (blockIdx.x * blockDim.x + threadIdx.x) >> 5;
    int lane = threadIdx.x & 31;
    if (gw >= NM + ND) return;
    int dir = (gw >= NM) ? 1 : 0;
    int row = dir ? gw - NM : gw;
    const int* off = dir ? g_off_d : g_off_m;
    const int* cur = dir ? g_cur_d : g_cur_m;
    const float* val = dir ? g_val_d : g_val_m;
    int s = off[row], e = cur[row];
    float sum = 0.f;
    for (int t = s + lane; t < e; t += 32) sum += val[t];
#pragma unroll
    for (int o = 16; o > 0; o >>= 1) sum += __shfl_down_sync(0xffffffffu, sum, o);
    if (lane == 0) {
        float r = (sum > 0.f) ? rsqrtf(sum) : 0.f;
        if (dir) g_rs_d[row] = r; else g_rs_m[row] = r;
    }
}

// ---------------- CSR SpMM (half gathers, vectorized col/val) -------------
// one warp per row; lane handles one half2 (2 of 64 cols)
// row start is 8-aligned -> int4/float4 loads are safe in the unrolled loop
__global__ __launch_bounds__(256) void spmm_kernel(float* __restrict__ outacc,
                                                   int dir, int store) {
    const int*     off  = dir ? g_off_d : g_off_m;
    const int*     cur  = dir ? g_cur_d : g_cur_m;
    const int*     col  = dir ? g_col_d : g_col_m;
    const float*   val  = dir ? g_val_d : g_val_m;
    const float*   invn = dir ? g_rs_d : g_rs_m;
    const __half2* xin  = dir ? g_membh : g_dembh;
    __half2*       xout = dir ? g_dembh : g_membh;
    int nrows = dir ? ND : NM;

    int gwarp = (blockIdx.x * blockDim.x + threadIdx.x) >> 5;
    int lane = threadIdx.x & 31;
    if (gwarp >= nrows) return;
    int t = off[gwarp], epos = cur[gwarp];

    float a0 = 0.f, a1 = 0.f;
    for (; t + 8 <= epos; t += 8) {
        int4   ca = *(const int4*)(col + t);
        int4   cb = *(const int4*)(col + t + 4);
        float4 va = *(const float4*)(val + t);
        float4 vb = *(const float4*)(val + t + 4);
        __half2 x0 = xin[(size_t)ca.x * 32 + lane];
        __half2 x1 = xin[(size_t)ca.y * 32 + lane];
        __half2 x2 = xin[(size_t)ca.z * 32 + lane];
        __half2 x3 = xin[(size_t)ca.w * 32 + lane];
        __half2 x4 = xin[(size_t)cb.x * 32 + lane];
        __half2 x5 = xin[(size_t)cb.y * 32 + lane];
        __half2 x6 = xin[(size_t)cb.z * 32 + lane];
        __half2 x7 = xin[(size_t)cb.w * 32 + lane];
        float2 f;
        f = __half22float2(x0); a0 += va.x * f.x; a1 += va.x * f.y;
        f = __half22float2(x1); a0 += va.y * f.x; a1 += va.y * f.y;
        f = __half22float2(x2); a0 += va.z * f.x; a1 += va.z * f.y;
        f = __half22float2(x3); a0 += va.w * f.x; a1 += va.w * f.y;
        f = __half22float2(x4); a0 += vb.x * f.x; a1 += vb.x * f.y;
        f = __half22float2(x5); a0 += vb.y * f.x; a1 += vb.y * f.y;
        f = __half22float2(x6); a0 += vb.z * f.x; a1 += vb.z * f.y;
        f = __half22float2(x7); a0 += vb.w * f.x; a1 += vb.w * f.y;
    }
    for (; t < epos; t++) {
        int c = col[t]; float v = val[t];
        float2 f = __half22float2(xin[(size_t)c * 32 + lane]);
        a0 += v * f.x; a1 += v * f.y;
    }
    float inv = invn[gwarp];
    float y0 = tanh_fast(a0 * inv);
    float y1 = tanh_fast(a1 * inv);
    xout[(size_t)gwarp * 32 + lane] = __float22half2_rn(make_float2(y0, y1));
    float* oa = outacc + (size_t)gwarp * DIM + lane * 2;
    if (store) { oa[0] = y0; oa[1] = y1; }
    else       { oa[0] += y0; oa[1] += y1; }
}

// ---------------- launch ----------------
extern "C" void kernel_launch(void* const* d_in, const int* in_sizes, int n_in,
                              void* d_out, int out_size) {
    const float* m_sim = (const float*)d_in[0];
    const float* d_sim = (const float*)d_in[1];
    const float* Wm    = (const float*)d_in[2];
    const float* Wd    = (const float*)d_in[3];
    const float* W1    = (const float*)d_in[4];
    const float* b1    = (const float*)d_in[5];
    const float* W2    = (const float*)d_in[6];
    const int*   mi    = (const int*)d_in[7];
    const int*   di    = (const int*)d_in[8];
    int E = in_sizes[7];
    float* out = (float*)d_out;

    zero_kernel<<<(NM + 255) / 256, 256>>>();
    proj_count_kernel<<<2 * GRID_PB + NCOUNT, 256>>>(m_sim, d_sim, Wm, Wd, mi, di, E);
    scan_kernel<<<2, 1024>>>();
    combine_kernel<<<((NM + ND) * DIM / 2 + 255) / 256, 256>>>();
    pre_mlp_both_kernel<<<GRID_PB, 256>>>(W1, b1);
    edge_csr_kernel<<<(E + 255) / 256, 256>>>(W2, mi, di, E);
    invnorm_kernel<<<((NM + ND) * 32 + 255) / 256, 256>>>();

    float* out_m = out;
    float* out_d = out + (size_t)NM * DIM;
    for (int l = 0; l < LAYERS; l++) {
        spmm_kernel<<<(NM * 32 + 255) / 256, 256>>>(out_m, 0, l == 0);
        spmm_kernel<<<(ND * 32 + 255) / 256, 256>>>(out_d, 1, l == 0);
    }
}

// round 9
// speedup vs baseline: 3.8948x; 1.0441x over previous
#include <cuda_runtime.h>
#include <cuda_fp16.h>

#define NM 12000
#define ND 10000
#define DIM 64
#define FEAT 512
#define EMAX 1000000
#define EPAD 1100000
#define LAYERS 3

#define PROJ_TILE 64
#define GRID_PROJ_M ((NM + PROJ_TILE - 1) / PROJ_TILE)   // 188
#define GRID_PROJ_D ((ND + PROJ_TILE - 1) / PROJ_TILE)   // 157
#define GRID_PB (GRID_PROJ_M + GRID_PROJ_D)              // 345
#define NCOUNT 512            // histogram blocks fused into proj launch

// ---------------- device scratch ----------------
__device__ float   g_memb[NM * DIM];
__device__ float   g_demb[ND * DIM];
__device__ __half2 g_membh[NM * DIM / 2];   // half mirror of embeddings
__device__ __half2 g_dembh[ND * DIM / 2];
__device__ __half2 g_pmh[NM * DIM / 2];     // half MLP partials (+b1 on m side)
__device__ __half2 g_pdh[ND * DIM / 2];
__device__ float   g_rs_m[NM];
__device__ float   g_rs_d[ND];
__device__ int     g_off_m[NM];         // 8-aligned row starts
__device__ int     g_off_d[ND];
__device__ int     g_cur_m[NM];         // counts -> cursors -> row ends
__device__ int     g_cur_d[ND];
__device__ int     g_col_m[EPAD];
__device__ float   g_val_m[EPAD];
__device__ int     g_col_d[EPAD];
__device__ float   g_val_d[EPAD];

__device__ __forceinline__ float tanh_fast(float x) {
    float xc = fminf(fmaxf(x, -12.f), 12.f);
    float e2 = __expf(2.f * xc);
    return __fdividef(e2 - 1.f, e2 + 1.f);
}
__device__ __forceinline__ float tanh_approx(float x) {
    float y;
    asm("tanh.approx.f32 %0, %1;" : "=f"(y) : "f"(x));
    return y;
}
__device__ __forceinline__ unsigned cvt_tf32(float f) {
    unsigned u;
    asm("cvt.rna.tf32.f32 %0, %1;" : "=r"(u) : "f"(f));
    return u;
}
__device__ __forceinline__ void mma_tf32(float* c, const unsigned* a, const unsigned* b) {
    asm("mma.sync.aligned.m16n8k8.row.col.f32.tf32.tf32.f32 "
        "{%0,%1,%2,%3}, {%4,%5,%6,%7}, {%8,%9}, {%0,%1,%2,%3};"
        : "+f"(c[0]), "+f"(c[1]), "+f"(c[2]), "+f"(c[3])
        : "r"(a[0]), "r"(a[1]), "r"(a[2]), "r"(a[3]), "r"(b[0]), "r"(b[1]));
}

// ---------------- init ----------------
__global__ void zero_kernel() {
    int i = blockIdx.x * blockDim.x + threadIdx.x;
    if (i < NM) g_cur_m[i] = 0;
    if (i < ND) g_cur_d[i] = 0;
}

// ---------------- tf32 MMA projection (m+d) + fused degree histogram ------
// blocks [0, GRID_PB): GEMM tiles 64x64; blocks [GRID_PB, +NCOUNT): histogram
// Writes fp32 emb AND half mirror in epilogue (replaces combine_kernel).
__global__ __launch_bounds__(128) void proj_mma_kernel(const float* __restrict__ Am,
                                                       const float* __restrict__ Ad,
                                                       const float* __restrict__ Wm,
                                                       const float* __restrict__ Wd,
                                                       const int* __restrict__ mi,
                                                       const int* __restrict__ di,
                                                       int E) {
    int bid = blockIdx.x;
    int tid = threadIdx.x;

    if (bid >= GRID_PB) {
        // -------- histogram part --------
        int b = bid - GRID_PB;
        for (int e = b * 128 + tid; e < E; e += NCOUNT * 128) {
            atomicAdd(&g_cur_m[mi[e]], 1);
            atomicAdd(&g_cur_d[di[e]], 1);
        }
        return;
    }

    int which = (bid >= GRID_PROJ_M) ? 1 : 0;
    int blk = which ? (bid - GRID_PROJ_M) : bid;
    const float* A = which ? Ad : Am;
    const float* W = which ? Wd : Wm;
    float* C = which ? g_demb : g_memb;
    __half2* Ch = which ? g_dembh : g_membh;
    int Mrows = which ? ND : NM;
    int row0 = blk * PROJ_TILE;

    __shared__ unsigned As[64 * 36];   // tf32 bits, stride 36 -> conflict-free frags
    __shared__ unsigned Ws[64 * 36];

    int lane = tid & 31;
    int warp = tid >> 5;
    int w0 = warp >> 1;      // row half (0/1)
    int w1 = warp & 1;       // col half (0/1)
    int g = lane >> 2, t = lane & 3;

    float acc[2][4][4];
#pragma unroll
    for (int i = 0; i < 2; i++)
#pragma unroll
        for (int j = 0; j < 4; j++)
#pragma unroll
            for (int k = 0; k < 4; k++) acc[i][j][k] = 0.f;

    for (int kc = 0; kc < FEAT; kc += 32) {
        // A tile 64x32 (guarded, zero-fill OOB rows)
#pragma unroll
        for (int p = 0; p < 4; p++) {
            int idx = p * 128 + tid;       // 0..511 float4 slots
            int r = idx >> 3, kq = idx & 7;
            int grow = row0 + r;
            float4 v = make_float4(0.f, 0.f, 0.f, 0.f);
            if (grow < Mrows)
                v = *(const float4*)(A + (size_t)grow * FEAT + kc + kq * 4);
            unsigned* dst = &As[r * 36 + kq * 4];
            dst[0] = cvt_tf32(v.x); dst[1] = cvt_tf32(v.y);
            dst[2] = cvt_tf32(v.z); dst[3] = cvt_tf32(v.w);
        }
        // W tile 64x32
#pragma unroll
        for (int p = 0; p < 4; p++) {
            int idx = p * 128 + tid;
            int c = idx >> 3, kq = idx & 7;
            float4 v = *(const float4*)(W + (size_t)c * FEAT + kc + kq * 4);
            unsigned* dst = &Ws[c * 36 + kq * 4];
            dst[0] = cvt_tf32(v.x); dst[1] = cvt_tf32(v.y);
            dst[2] = cvt_tf32(v.z); dst[3] = cvt_tf32(v.w);
        }
        __syncthreads();
#pragma unroll
        for (int kk = 0; kk < 32; kk += 8) {
            unsigned a[2][4], b[4][2];
#pragma unroll
            for (int m2 = 0; m2 < 2; m2++) {
                int r = w0 * 32 + m2 * 16;
                a[m2][0] = As[(r + g) * 36 + kk + t];
                a[m2][1] = As[(r + g + 8) * 36 + kk + t];
                a[m2][2] = As[(r + g) * 36 + kk + t + 4];
                a[m2][3] = As[(r + g + 8) * 36 + kk + t + 4];
            }
#pragma unroll
            for (int ni = 0; ni < 4; ni++) {
                int c = w1 * 32 + ni * 8;
                b[ni][0] = Ws[(c + g) * 36 + kk + t];
                b[ni][1] = Ws[(c + g) * 36 + kk + t + 4];
            }
#pragma unroll
            for (int m2 = 0; m2 < 2; m2++)
#pragma unroll
                for (int ni = 0; ni < 4; ni++)
                    mma_tf32(acc[m2][ni], a[m2], b[ni]);
        }
        __syncthreads();
    }

    // epilogue: fp32 emb + half mirror
#pragma unroll
    for (int m2 = 0; m2 < 2; m2++) {
#pragma unroll
        for (int rr = 0; rr < 2; rr++) {
            int grow = row0 + w0 * 32 + m2 * 16 + g + rr * 8;
            if (grow < Mrows) {
#pragma unroll
                for (int ni = 0; ni < 4; ni++) {
                    float c0 = acc[m2][ni][rr * 2 + 0];
                    float c1 = acc[m2][ni][rr * 2 + 1];
                    int col = w1 * 32 + ni * 8 + 2 * t;
                    *(float2*)(C + (size_t)grow * DIM + col) = make_float2(c0, c1);
                    Ch[(size_t)grow * 32 + (col >> 1)] =
                        __float22half2_rn(make_float2(c0, c1));
                }
            }
        }
    }
}

// ---------------- exclusive scan with 8-alignment padding -----------------
__global__ void scan_kernel() {
    int which = blockIdx.x;
    int n = which ? ND : NM;                 // both divisible by 16
    int* cnt = which ? g_cur_d : g_cur_m;
    int* off = which ? g_off_d : g_off_m;
    __shared__ int part[1024];
    int t = threadIdx.x;
    int nth = n >> 4;
    int base = t << 4;

    int4 c[4];
    int s = 0;
    if (t < nth) {
#pragma unroll
        for (int q = 0; q < 4; q++)
            c[q] = *(const int4*)(cnt + base + q * 4);
        const int* cp = (const int*)c;
#pragma unroll
        for (int q = 0; q < 16; q++) s += (cp[q] + 7) & ~7;
    }
    part[t] = s;
    __syncthreads();
    for (int dd = 1; dd < 1024; dd <<= 1) {
        int v = (t >= dd) ? part[t - dd] : 0;
        __syncthreads();
        part[t] += v;
        __syncthreads();
    }
    if (t < nth) {
        int run = (t == 0) ? 0 : part[t - 1];
        const int* cp = (const int*)c;
        int o[16];
#pragma unroll
        for (int q = 0; q < 16; q++) { o[q] = run; run += (cp[q] + 7) & ~7; }
#pragma unroll
        for (int q = 0; q < 4; q++) {
            *(int4*)(off + base + q * 4) = ((const int4*)o)[q];
            *(int4*)(cnt + base + q * 4) = ((const int4*)o)[q];
        }
    }
}

// ---------------- per-node MLP partials -> half2 (m and d merged) ---------
__global__ __launch_bounds__(256) void pre_mlp_both_kernel(const float* __restrict__ W1,
                                                           const float* __restrict__ b1) {
    int which = (blockIdx.x >= GRID_PROJ_M) ? 1 : 0;
    int blk = which ? (blockIdx.x - GRID_PROJ_M) : blockIdx.x;
    const float* X = which ? g_demb : g_memb;
    __half2* P = which ? g_pdh : g_pmh;
    int Mrows = which ? ND : NM;
    int koff = which ? 64 : 0;

    __shared__ float As[PROJ_TILE * 33];
    __shared__ float WsT[32 * 64];
    int tid = threadIdx.x;
    int tx = tid & 15, ty = tid >> 4;
    int row0 = blk * PROJ_TILE;

    float acc[4][4];
#pragma unroll
    for (int i = 0; i < 4; i++)
#pragma unroll
        for (int j = 0; j < 4; j++) acc[i][j] = 0.f;

    for (int kc = 0; kc < DIM; kc += 32) {
#pragma unroll
        for (int p = 0; p < 2; p++) {
            int idx = p * 256 + tid;
            int r = idx >> 3;
            int kq = idx & 7;
            int grow = row0 + r;
            float4 v = make_float4(0.f, 0.f, 0.f, 0.f);
            if (grow < Mrows)
                v = *(const float4*)(X + (size_t)grow * DIM + kc + kq * 4);
            float* dst = &As[r * 33 + kq * 4];
            dst[0] = fmaxf(v.x, 0.f); dst[1] = fmaxf(v.y, 0.f);
            dst[2] = fmaxf(v.z, 0.f); dst[3] = fmaxf(v.w, 0.f);
        }
#pragma unroll
        for (int p = 0; p < 2; p++) {
            int idx = p * 256 + tid;
            int c = idx >> 3;
            int kq = idx & 7;
            float4 v = *(const float4*)(W1 + (size_t)c * 128 + koff + kc + kq * 4);
            WsT[(kq * 4 + 0) * 64 + c] = v.x;
            WsT[(kq * 4 + 1) * 64 + c] = v.y;
            WsT[(kq * 4 + 2) * 64 + c] = v.z;
            WsT[(kq * 4 + 3) * 64 + c] = v.w;
        }
        __syncthreads();
#pragma unroll 8
        for (int k = 0; k < 32; k++) {
            float4 w = *(const float4*)&WsT[k * 64 + tx * 4];
#pragma unroll
            for (int i = 0; i < 4; i++) {
                float a = As[(ty * 4 + i) * 33 + k];
                acc[i][0] += a * w.x; acc[i][1] += a * w.y;
                acc[i][2] += a * w.z; acc[i][3] += a * w.w;
            }
        }
        __syncthreads();
    }
#pragma unroll
    for (int i = 0; i < 4; i++) {
        int grow = row0 + ty * 4 + i;
        if (grow < Mrows) {
            float4 v = make_float4(acc[i][0], acc[i][1], acc[i][2], acc[i][3]);
            if (!which) {   // fold bias into m-side partial
                float4 bb = *(const float4*)(b1 + tx * 4);
                v.x += bb.x; v.y += bb.y; v.z += bb.z; v.w += bb.w;
            }
            P[(size_t)grow * 32 + tx * 2 + 0] = __float22half2_rn(make_float2(v.x, v.y));
            P[(size_t)grow * 32 + tx * 2 + 1] = __float22half2_rn(make_float2(v.z, v.w));
        }
    }
}

// ---------------- per-edge: gather half partials, tanh, dot, exp, scatter --
__global__ __launch_bounds__(256) void edge_csr_kernel(const float* __restrict__ W2,
                                                       const int* __restrict__ mi,
                                                       const int* __restrict__ di,
                                                       int E) {
    __shared__ float sW2[64];
    int tid = threadIdx.x;
    if (tid < 64) sW2[tid] = W2[tid];
    __syncthreads();

    int e = blockIdx.x * blockDim.x + tid;
    if (e >= E) return;
    int m = mi[e], d = di[e];

    const uint4* pm = (const uint4*)(g_pmh + (size_t)m * 32);  // 8 x uint4 per row
    const uint4* pd = (const uint4*)(g_pdh + (size_t)d * 32);

    float score = 0.f;
#pragma unroll
    for (int q = 0; q < 8; q++) {
        uint4 ua = pm[q];
        uint4 ub = pd[q];
        const unsigned* ap = (const unsigned*)&ua;
        const unsigned* bp = (const unsigned*)&ub;
#pragma unroll
        for (int s = 0; s < 4; s++) {
            float2 fa = __half22float2(*(const __half2*)&ap[s]);
            float2 fb = __half22float2(*(const __half2*)&bp[s]);
            int j = q * 8 + s * 2;
            score += tanh_approx(fa.x + fb.x) * sW2[j + 0];
            score += tanh_approx(fa.y + fb.y) * sW2[j + 1];
        }
    }
    float w = __expf(score);
    int pmpos = atomicAdd(&g_cur_m[m], 1);
    g_col_m[pmpos] = d; g_val_m[pmpos] = w;
    int pdpos = atomicAdd(&g_cur_d[d], 1);
    g_col_d[pdpos] = m; g_val_d[pdpos] = w;
}

// ---------------- row sums from CSR vals -> rs^{-0.5} (warp per row) ------
__global__ __launch_bounds__(256) void invnorm_kernel() {
    int gw = (blockIdx.x * blockDim.x + threadIdx.x) >> 5;
    int lane = threadIdx.x & 31;
    if (gw >= NM + ND) return;
    int dir = (gw >= NM) ? 1 : 0;
    int row = dir ? gw - NM : gw;
    const int* off = dir ? g_off_d : g_off_m;
    const int* cur = dir ? g_cur_d : g_cur_m;
    const float* val = dir ? g_val_d : g_val_m;
    int s = off[row], e = cur[row];
    float sum = 0.f;
    for (int t = s + lane; t < e; t += 32) sum += val[t];
#pragma unroll
    for (int o = 16; o > 0; o >>= 1) sum += __shfl_down_sync(0xffffffffu, sum, o);
    if (lane == 0) {
        float r = (sum > 0.f) ? rsqrtf(sum) : 0.f;
        if (dir) g_rs_d[row] = r; else g_rs_m[row] = r;
    }
}

// ---------------- CSR SpMM (half gathers, vectorized col/val) -------------
__global__ __launch_bounds__(256) void spmm_kernel(float* __restrict__ outacc,
                                                   int dir, int store) {
    const int*     off  = dir ? g_off_d : g_off_m;
    const int*     cur  = dir ? g_cur_d : g_cur_m;
    const int*     col  = dir ? g_col_d : g_col_m;
    const float*   val  = dir ? g_val_d : g_val_m;
    const float*   invn = dir ? g_rs_d : g_rs_m;
    const __half2* xin  = dir ? g_membh : g_dembh;
    __half2*       xout = dir ? g_dembh : g_membh;
    int nrows = dir ? ND : NM;

    int gwarp = (blockIdx.x * blockDim.x + threadIdx.x) >> 5;
    int lane = threadIdx.x & 31;
    if (gwarp >= nrows) return;
    int t = off[gwarp], epos = cur[gwarp];

    float a0 = 0.f, a1 = 0.f;
    for (; t + 8 <= epos; t += 8) {
        int4   ca = *(const int4*)(col + t);
        int4   cb = *(const int4*)(col + t + 4);
        float4 va = *(const float4*)(val + t);
        float4 vb = *(const float4*)(val + t + 4);
        __half2 x0 = xin[(size_t)ca.x * 32 + lane];
        __half2 x1 = xin[(size_t)ca.y * 32 + lane];
        __half2 x2 = xin[(size_t)ca.z * 32 + lane];
        __half2 x3 = xin[(size_t)ca.w * 32 + lane];
        __half2 x4 = xin[(size_t)cb.x * 32 + lane];
        __half2 x5 = xin[(size_t)cb.y * 32 + lane];
        __half2 x6 = xin[(size_t)cb.z * 32 + lane];
        __half2 x7 = xin[(size_t)cb.w * 32 + lane];
        float2 f;
        f = __half22float2(x0); a0 += va.x * f.x; a1 += va.x * f.y;
        f = __half22float2(x1); a0 += va.y * f.x; a1 += va.y * f.y;
        f = __half22float2(x2); a0 += va.z * f.x; a1 += va.z * f.y;
        f = __half22float2(x3); a0 += va.w * f.x; a1 += va.w * f.y;
        f = __half22float2(x4); a0 += vb.x * f.x; a1 += vb.x * f.y;
        f = __half22float2(x5); a0 += vb.y * f.x; a1 += vb.y * f.y;
        f = __half22float2(x6); a0 += vb.z * f.x; a1 += vb.z * f.y;
        f = __half22float2(x7); a0 += vb.w * f.x; a1 += vb.w * f.y;
    }
    for (; t < epos; t++) {
        int c = col[t]; float v = val[t];
        float2 f = __half22float2(xin[(size_t)c * 32 + lane]);
        a0 += v * f.x; a1 += v * f.y;
    }
    float inv = invn[gwarp];
    float y0 = tanh_fast(a0 * inv);
    float y1 = tanh_fast(a1 * inv);
    xout[(size_t)gwarp * 32 + lane] = __float22half2_rn(make_float2(y0, y1));
    float* oa = outacc + (size_t)gwarp * DIM + lane * 2;
    if (store) { oa[0] = y0; oa[1] = y1; }
    else       { oa[0] += y0; oa[1] += y1; }
}

// ---------------- launch ----------------
extern "C" void kernel_launch(void* const* d_in, const int* in_sizes, int n_in,
                              void* d_out, int out_size) {
    const float* m_sim = (const float*)d_in[0];
    const float* d_sim = (const float*)d_in[1];
    const float* Wm    = (const float*)d_in[2];
    const float* Wd    = (const float*)d_in[3];
    const float* W1    = (const float*)d_in[4];
    const float* b1    = (const float*)d_in[5];
    const float* W2    = (const float*)d_in[6];
    const int*   mi    = (const int*)d_in[7];
    const int*   di    = (const int*)d_in[8];
    int E = in_sizes[7];
    float* out = (float*)d_out;

    zero_kernel<<<(NM + 255) / 256, 256>>>();
    proj_mma_kernel<<<GRID_PB + NCOUNT, 128>>>(m_sim, d_sim, Wm, Wd, mi, di, E);
    scan_kernel<<<2, 1024>>>();
    pre_mlp_both_kernel<<<GRID_PB, 256>>>(W1, b1);
    edge_csr_kernel<<<(E + 255) / 256, 256>>>(W2, mi, di, E);
    invnorm_kernel<<<((NM + ND) * 32 + 255) / 256, 256>>>();

    float* out_m = out;
    float* out_d = out + (size_t)NM * DIM;
    for (int l = 0; l < LAYERS; l++) {
        spmm_kernel<<<(NM * 32 + 255) / 256, 256>>>(out_m, 0, l == 0);
        spmm_kernel<<<(ND * 32 + 255) / 256, 256>>>(out_d, 1, l == 0);
    }
}